// round 5
// baseline (speedup 1.0000x reference)
#include <cuda_runtime.h>
#include <cstdint>
#include <math.h>

#define BATCH  16384
#define DMODEL 2048
#define RANK   64
#define NPROJ  192

// ---------------------------------------------------------------------------
// helpers
// ---------------------------------------------------------------------------
__device__ __forceinline__ float tf32r(float v) {
    uint32_t u;
    asm("cvt.rna.tf32.f32 %0, %1;" : "=r"(u) : "f"(v));
    return __uint_as_float(u);
}

// D += A(16x8,row) * B(8x8,col)  tf32 inputs, f32 accum
__device__ __forceinline__ void mma_tf32(float* d, const float* a, const float* b) {
    const uint32_t* A = reinterpret_cast<const uint32_t*>(a);
    const uint32_t* B = reinterpret_cast<const uint32_t*>(b);
    asm volatile(
        "mma.sync.aligned.m16n8k8.row.col.f32.tf32.tf32.f32 "
        "{%0,%1,%2,%3}, {%4,%5,%6,%7}, {%8,%9}, {%0,%1,%2,%3};\n"
        : "+f"(d[0]), "+f"(d[1]), "+f"(d[2]), "+f"(d[3])
        : "r"(A[0]), "r"(A[1]), "r"(A[2]), "r"(A[3]), "r"(B[0]), "r"(B[1]));
}

// ---------------------------------------------------------------------------
// Kernel 1: P = x @ [W_dt;W_ph;W_B]^T  (M=16384, N=192, K=2048)
// CTA 256 thr, tile 128 x 192, BK=32, DOUBLE-buffered smem, 1 barrier/iter.
// Warp grid 2x4 -> warp tile 64x48.  Fused elementwise epilogue.
// ---------------------------------------------------------------------------
#define LDK   36            // 32 + 4 pad: conflict-free fragment LDS
#define ASZ   (128 * LDK)   // floats per A buffer
#define BSZ   (192 * LDK)   // floats per B buffer
#define LDP   194           // P stage leading dim (even -> aligned float2)
#define NKT   (DMODEL / 32) // 64 K-tiles
#define SMEM1 (128 * LDP * 4)   // 99328 B  (> 2*(ASZ+BSZ)*4 = 92160 B)

__global__ void __launch_bounds__(256, 1) proj_kernel(
    const float* __restrict__ x,
    const float* __restrict__ sre, const float* __restrict__ sim_,
    const float* __restrict__ Wdt, const float* __restrict__ bdt,
    const float* __restrict__ Wph, const float* __restrict__ bph,
    const float* __restrict__ WB,
    const float* __restrict__ Areal, const float* __restrict__ Aimag,
    float* __restrict__ nre, float* __restrict__ nim)
{
    extern __shared__ float smemf[];
    float* sA[2] = { smemf, smemf + ASZ };
    float* sB[2] = { smemf + 2 * ASZ, smemf + 2 * ASZ + BSZ };

    const int tid  = threadIdx.x;
    const int wid  = tid >> 5;
    const int lane = tid & 31;
    const int g    = lane >> 2;
    const int t    = lane & 3;
    const int wm   = wid >> 2;     // 0..1  (64 rows)
    const int wn   = wid & 3;      // 0..3  (48 cols)
    const int m0   = blockIdx.x * 128;

    // ---- per-thread global pointers + smem offsets (loop-invariant) ----
    const float* aP[4]; int aOfs[4];
    #pragma unroll
    for (int i = 0; i < 4; i++) {
        int idx = tid + i * 256;               // A: 128 rows x 8 float4
        int row = idx >> 3, c4 = (idx & 7) << 2;
        aP[i]   = x + (size_t)(m0 + row) * DMODEL + c4;
        aOfs[i] = row * LDK + c4;
    }
    const float* bP[6]; int bOfs[6];
    #pragma unroll
    for (int i = 0; i < 6; i++) {
        int idx = tid + i * 256;               // B: 192 rows x 8 float4
        int row = idx >> 3, c4 = (idx & 7) << 2;
        const float* W = (row < 64)  ? (Wdt + (size_t)row * DMODEL)
                       : (row < 128) ? (Wph + (size_t)(row - 64) * DMODEL)
                                     : (WB  + (size_t)(row - 128) * DMODEL);
        bP[i]   = W + c4;
        bOfs[i] = row * LDK + c4;
    }

    float acc[4][6][4];
    #pragma unroll
    for (int i = 0; i < 4; i++)
        #pragma unroll
        for (int j = 0; j < 6; j++)
            #pragma unroll
            for (int k = 0; k < 4; k++) acc[i][j][k] = 0.f;

    float4 ra[4], rb[6];
    auto ldg = [&](int kt) {
        #pragma unroll
        for (int i = 0; i < 4; i++)
            ra[i] = *reinterpret_cast<const float4*>(aP[i] + kt * 32);
        #pragma unroll
        for (int i = 0; i < 6; i++)
            rb[i] = *reinterpret_cast<const float4*>(bP[i] + kt * 32);
    };
    auto sts = [&](int b) {
        #pragma unroll
        for (int i = 0; i < 4; i++) {
            float4 v = ra[i], w;
            w.x = tf32r(v.x); w.y = tf32r(v.y); w.z = tf32r(v.z); w.w = tf32r(v.w);
            *reinterpret_cast<float4*>(sA[b] + aOfs[i]) = w;
        }
        #pragma unroll
        for (int i = 0; i < 6; i++) {
            float4 v = rb[i], w;
            w.x = tf32r(v.x); w.y = tf32r(v.y); w.z = tf32r(v.z); w.w = tf32r(v.w);
            *reinterpret_cast<float4*>(sB[b] + bOfs[i]) = w;
        }
    };

    // ---- prologue ----
    ldg(0); sts(0); ldg(1);
    __syncthreads();

    // ---- main loop: 1 barrier per K-tile ----
    for (int kt = 0; kt < NKT; ++kt) {
        const int b = kt & 1;
        if (kt + 1 < NKT) {
            sts(b ^ 1);                          // regs hold tile kt+1
            if (kt + 2 < NKT) ldg(kt + 2);       // prefetch under the MMAs
        }
        const float* cA = sA[b];
        const float* cB = sB[b];
        #pragma unroll
        for (int k8 = 0; k8 < 4; k8++) {
            int kk = k8 * 8;
            float afr[4][4], bfr[6][2];
            #pragma unroll
            for (int mt = 0; mt < 4; mt++) {
                int rb0 = wm * 64 + mt * 16;
                afr[mt][0] = cA[(rb0 + g)     * LDK + kk + t];
                afr[mt][1] = cA[(rb0 + g + 8) * LDK + kk + t];
                afr[mt][2] = cA[(rb0 + g)     * LDK + kk + t + 4];
                afr[mt][3] = cA[(rb0 + g + 8) * LDK + kk + t + 4];
            }
            #pragma unroll
            for (int nt = 0; nt < 6; nt++) {
                int nb = wn * 48 + nt * 8;
                bfr[nt][0] = cB[(nb + g) * LDK + kk + t];
                bfr[nt][1] = cB[(nb + g) * LDK + kk + t + 4];
            }
            #pragma unroll
            for (int mt = 0; mt < 4; mt++)
                #pragma unroll
                for (int nt = 0; nt < 6; nt++)
                    mma_tf32(acc[mt][nt], afr[mt], bfr[nt]);
        }
        __syncthreads();
    }

    // ---- stage P (128 x 192) into smem ----
    float* P = smemf;
    #pragma unroll
    for (int mt = 0; mt < 4; mt++) {
        int r0 = wm * 64 + mt * 16 + g;
        #pragma unroll
        for (int nt = 0; nt < 6; nt++) {
            int c0 = wn * 48 + nt * 8 + 2 * t;
            *reinterpret_cast<float2*>(P + r0 * LDP + c0) =
                make_float2(acc[mt][nt][0], acc[mt][nt][1]);
            *reinterpret_cast<float2*>(P + (r0 + 8) * LDP + c0) =
                make_float2(acc[mt][nt][2], acc[mt][nt][3]);
        }
    }
    __syncthreads();

    // ---- fused elementwise state update (128 rows x 64 ranks) ----
    const float PI_F = 3.14159265358979323846f;
    const int r = tid & 63;                     // constant per thread
    const float bdt_r = bdt[r];
    const float bph_r = bph[r];
    const float eA_r  = expf(Areal[r]);
    const float Ai_r  = Aimag[r];

    #pragma unroll
    for (int i = 0; i < 32; i++) {
        int idx  = tid + i * 256;
        int row  = idx >> 6;
        int grow = m0 + row;

        float zdt   = P[row * LDP + r] + bdt_r;
        float dt    = (zdt > 20.f) ? zdt : log1pf(expf(zdt));
        float zph   = P[row * LDP + 64 + r] + bph_r;
        float phase = tanhf(zph) * PI_F;
        float decay = expf(-dt * eA_r);
        float angle = fmaf(dt, Ai_r, phase);
        float Bv    = P[row * LDP + 128 + r];

        float sn, cs;
        sincosf(angle, &sn, &cs);

        float a_ = sre[(size_t)grow * RANK + r];
        float b_ = sim_[(size_t)grow * RANK + r];

        nre[(size_t)grow * RANK + r] = fmaf(a_ * cs - b_ * sn, decay, Bv);
        nim[(size_t)grow * RANK + r] = (a_ * sn + b_ * cs) * decay;
    }
}

// ---------------------------------------------------------------------------
// Kernel 2: out = new_re @ W_C^T  (M=16384, N=2048, K=64)
// CTA 256 thr, tile 64 x 128, whole K in smem. Small acc -> 3+ resident CTAs
// for store-concurrency (kernel is DRAM-write-bound).
// ---------------------------------------------------------------------------
#define LDK2 68

__global__ void __launch_bounds__(256, 3) out_kernel(
    const float* __restrict__ nre,
    const float* __restrict__ WC,
    float* __restrict__ out)
{
    extern __shared__ float smemf[];
    float* sA = smemf;                  // 64  x LDK2
    float* sB = smemf + 64 * LDK2;      // 128 x LDK2

    const int tid  = threadIdx.x;
    const int wid  = tid >> 5;
    const int lane = tid & 31;
    const int g    = lane >> 2;
    const int t    = lane & 3;
    const int wm   = wid >> 2;          // 0..1 (32 rows each)
    const int wn   = wid & 3;           // 0..3 (32 cols each)
    const int m0   = blockIdx.x * 64;
    const int n0   = blockIdx.y * 128;

    #pragma unroll
    for (int i = 0; i < 4; i++) {       // A: 64 rows x 16 float4
        int idx = tid + i * 256;
        int row = idx >> 4, c4 = (idx & 15) << 2;
        float4 v = *reinterpret_cast<const float4*>(nre + (size_t)(m0 + row) * RANK + c4);
        float4 w;
        w.x = tf32r(v.x); w.y = tf32r(v.y); w.z = tf32r(v.z); w.w = tf32r(v.w);
        *reinterpret_cast<float4*>(sA + row * LDK2 + c4) = w;
    }
    #pragma unroll
    for (int i = 0; i < 8; i++) {       // B: 128 rows x 16 float4
        int idx = tid + i * 256;
        int row = idx >> 4, c4 = (idx & 15) << 2;
        float4 v = *reinterpret_cast<const float4*>(WC + (size_t)(n0 + row) * RANK + c4);
        float4 w;
        w.x = tf32r(v.x); w.y = tf32r(v.y); w.z = tf32r(v.z); w.w = tf32r(v.w);
        *reinterpret_cast<float4*>(sB + row * LDK2 + c4) = w;
    }
    __syncthreads();

    float acc[2][4][4];
    #pragma unroll
    for (int i = 0; i < 2; i++)
        #pragma unroll
        for (int j = 0; j < 4; j++)
            #pragma unroll
            for (int k = 0; k < 4; k++) acc[i][j][k] = 0.f;

    #pragma unroll
    for (int k8 = 0; k8 < 8; k8++) {
        int kk = k8 * 8;
        float afr[2][4], bfr[4][2];
        #pragma unroll
        for (int mt = 0; mt < 2; mt++) {
            int rb0 = wm * 32 + mt * 16;
            afr[mt][0] = sA[(rb0 + g)     * LDK2 + kk + t];
            afr[mt][1] = sA[(rb0 + g + 8) * LDK2 + kk + t];
            afr[mt][2] = sA[(rb0 + g)     * LDK2 + kk + t + 4];
            afr[mt][3] = sA[(rb0 + g + 8) * LDK2 + kk + t + 4];
        }
        #pragma unroll
        for (int nt = 0; nt < 4; nt++) {
            int nb = wn * 32 + nt * 8;
            bfr[nt][0] = sB[(nb + g) * LDK2 + kk + t];
            bfr[nt][1] = sB[(nb + g) * LDK2 + kk + t + 4];
        }
        #pragma unroll
        for (int mt = 0; mt < 2; mt++)
            #pragma unroll
            for (int nt = 0; nt < 4; nt++)
                mma_tf32(acc[mt][nt], afr[mt], bfr[nt]);
    }

    #pragma unroll
    for (int mt = 0; mt < 2; mt++) {
        int row = m0 + wm * 32 + mt * 16 + g;
        #pragma unroll
        for (int nt = 0; nt < 4; nt++) {
            int col = n0 + wn * 32 + nt * 8 + 2 * t;
            *reinterpret_cast<float2*>(out + (size_t)row * DMODEL + col) =
                make_float2(acc[mt][nt][0], acc[mt][nt][1]);
            *reinterpret_cast<float2*>(out + (size_t)(row + 8) * DMODEL + col) =
                make_float2(acc[mt][nt][2], acc[mt][nt][3]);
        }
    }
}

// ---------------------------------------------------------------------------
// launch
// ---------------------------------------------------------------------------
extern "C" void kernel_launch(void* const* d_in, const int* in_sizes, int n_in,
                              void* d_out, int out_size)
{
    const float* x    = (const float*)d_in[0];
    const float* sre  = (const float*)d_in[1];
    const float* sim_ = (const float*)d_in[2];
    const float* Wdt  = (const float*)d_in[3];
    const float* bdt  = (const float*)d_in[4];
    const float* Wph  = (const float*)d_in[5];
    const float* bph  = (const float*)d_in[6];
    const float* WB   = (const float*)d_in[7];
    const float* WC   = (const float*)d_in[8];
    const float* Ar   = (const float*)d_in[9];
    const float* Ai   = (const float*)d_in[10];

    float* out = (float*)d_out;
    float* nre = out + (size_t)BATCH * DMODEL;
    float* nim = nre + (size_t)BATCH * RANK;

    const int smem1 = SMEM1;                                  // 99328 B
    const int smem2 = (64 + 128) * LDK2 * sizeof(float);      // 52224 B

    cudaFuncSetAttribute(proj_kernel, cudaFuncAttributeMaxDynamicSharedMemorySize, smem1);
    cudaFuncSetAttribute(out_kernel,  cudaFuncAttributeMaxDynamicSharedMemorySize, smem2);

    proj_kernel<<<BATCH / 128, 256, smem1>>>(x, sre, sim_, Wdt, bdt, Wph, bph, WB,
                                             Ar, Ai, nre, nim);
    out_kernel<<<dim3(BATCH / 64, DMODEL / 128), 256, smem2>>>(nre, WC, out);
}

// round 6
// speedup vs baseline: 1.0501x; 1.0501x over previous
#include <cuda_runtime.h>
#include <cstdint>
#include <math.h>

#define BATCH  16384
#define DMODEL 2048
#define RANK   64
#define NPROJ  192

// ---------------------------------------------------------------------------
// helpers
// ---------------------------------------------------------------------------
__device__ __forceinline__ float tf32r(float v) {
    uint32_t u;
    asm("cvt.rna.tf32.f32 %0, %1;" : "=r"(u) : "f"(v));
    return __uint_as_float(u);
}

// D += A(16x8,row) * B(8x8,col)  tf32 inputs, f32 accum
__device__ __forceinline__ void mma_tf32(float* d, const float* a, const float* b) {
    const uint32_t* A = reinterpret_cast<const uint32_t*>(a);
    const uint32_t* B = reinterpret_cast<const uint32_t*>(b);
    asm volatile(
        "mma.sync.aligned.m16n8k8.row.col.f32.tf32.tf32.f32 "
        "{%0,%1,%2,%3}, {%4,%5,%6,%7}, {%8,%9}, {%0,%1,%2,%3};\n"
        : "+f"(d[0]), "+f"(d[1]), "+f"(d[2]), "+f"(d[3])
        : "r"(A[0]), "r"(A[1]), "r"(A[2]), "r"(A[3]), "r"(B[0]), "r"(B[1]));
}

// ---------------------------------------------------------------------------
// Kernel 1: P = x @ [W_dt;W_ph;W_B]^T  (M=16384, N=192, K=2048)
// CTA 256 thr, tile 64 x 192, BK=32. DOUBLE-buffered smem, ONE barrier/iter.
// grid 256 -> 2 CTAs/SM. Warp grid 2x4 (warp 32x48, acc 48 regs).
// Fused elementwise epilogue -> new_re, new_im.
// ---------------------------------------------------------------------------
#define LDK   36                 // 32 + 4 pad: conflict-free fragment LDS
#define ASZ   (64  * LDK)        // floats per A buffer  (2304)
#define BSZ   (192 * LDK)        // floats per B buffer  (6912)
#define LDP   194                // P stage leading dim
#define NKT   (DMODEL / 32)      // 64 K-tiles
#define SMEM1 (2 * (ASZ + BSZ) * 4)   // 73728 B  (>= P stage 64*194*4 = 49664)

__global__ void __launch_bounds__(256, 2) proj_kernel(
    const float* __restrict__ x,
    const float* __restrict__ sre, const float* __restrict__ sim_,
    const float* __restrict__ Wdt, const float* __restrict__ bdt,
    const float* __restrict__ Wph, const float* __restrict__ bph,
    const float* __restrict__ WB,
    const float* __restrict__ Areal, const float* __restrict__ Aimag,
    float* __restrict__ nre, float* __restrict__ nim)
{
    extern __shared__ float smemf[];
    float* sA[2] = { smemf, smemf + ASZ };
    float* sB[2] = { smemf + 2 * ASZ, smemf + 2 * ASZ + BSZ };

    const int tid  = threadIdx.x;
    const int wid  = tid >> 5;
    const int lane = tid & 31;
    const int g    = lane >> 2;
    const int t    = lane & 3;
    const int wm   = wid >> 2;     // 0..1  (32 rows)
    const int wn   = wid & 3;      // 0..3  (48 cols)
    const int m0   = blockIdx.x * 64;

    // per-thread load geometry (loop-invariant)
    // A: 64 rows x 8 float4 = 512 float4 -> 2/thread
    // B: 192 rows x 8 float4 = 1536 float4 -> 6/thread
    const float* aP[2]; int aOfs[2];
    #pragma unroll
    for (int i = 0; i < 2; i++) {
        int idx = tid + i * 256;
        int row = idx >> 3, c4 = (idx & 7) << 2;
        aP[i]   = x + (size_t)(m0 + row) * DMODEL + c4;
        aOfs[i] = row * LDK + c4;
    }
    const float* bP[6]; int bOfs[6];
    #pragma unroll
    for (int i = 0; i < 6; i++) {
        int idx = tid + i * 256;
        int row = idx >> 3, c4 = (idx & 7) << 2;
        const float* W = (row < 64)  ? (Wdt + (size_t)row * DMODEL)
                       : (row < 128) ? (Wph + (size_t)(row - 64) * DMODEL)
                                     : (WB  + (size_t)(row - 128) * DMODEL);
        bP[i]   = W + c4;
        bOfs[i] = row * LDK + c4;
    }

    float acc[2][6][4];
    #pragma unroll
    for (int i = 0; i < 2; i++)
        #pragma unroll
        for (int j = 0; j < 6; j++)
            #pragma unroll
            for (int k = 0; k < 4; k++) acc[i][j][k] = 0.f;

    float4 ra[2], rb[6];
    auto ldg = [&](int kt) {
        #pragma unroll
        for (int i = 0; i < 2; i++)
            ra[i] = *reinterpret_cast<const float4*>(aP[i] + kt * 32);
        #pragma unroll
        for (int i = 0; i < 6; i++)
            rb[i] = *reinterpret_cast<const float4*>(bP[i] + kt * 32);
    };
    auto sts = [&](int b) {
        #pragma unroll
        for (int i = 0; i < 2; i++) {
            float4 v = ra[i], w;
            w.x = tf32r(v.x); w.y = tf32r(v.y); w.z = tf32r(v.z); w.w = tf32r(v.w);
            *reinterpret_cast<float4*>(sA[b] + aOfs[i]) = w;
        }
        #pragma unroll
        for (int i = 0; i < 6; i++) {
            float4 v = rb[i], w;
            w.x = tf32r(v.x); w.y = tf32r(v.y); w.z = tf32r(v.z); w.w = tf32r(v.w);
            *reinterpret_cast<float4*>(sB[b] + bOfs[i]) = w;
        }
    };

    // prologue: tile 0 -> buf0, tile 1 -> regs
    ldg(0); sts(0); ldg(1);
    __syncthreads();

    // main loop: ONE barrier per K-tile
    for (int kt = 0; kt < NKT; ++kt) {
        const int b = kt & 1;
        if (kt + 1 < NKT) {
            sts(b ^ 1);                          // regs hold tile kt+1
            if (kt + 2 < NKT) ldg(kt + 2);       // prefetch under the MMAs
        }
        const float* cA = sA[b];
        const float* cB = sB[b];
        #pragma unroll
        for (int k8 = 0; k8 < 4; k8++) {
            int kk = k8 * 8;
            float afr[2][4], bfr[6][2];
            #pragma unroll
            for (int mt = 0; mt < 2; mt++) {
                int rb0 = wm * 32 + mt * 16;
                afr[mt][0] = cA[(rb0 + g)     * LDK + kk + t];
                afr[mt][1] = cA[(rb0 + g + 8) * LDK + kk + t];
                afr[mt][2] = cA[(rb0 + g)     * LDK + kk + t + 4];
                afr[mt][3] = cA[(rb0 + g + 8) * LDK + kk + t + 4];
            }
            #pragma unroll
            for (int nt = 0; nt < 6; nt++) {
                int nb = wn * 48 + nt * 8;
                bfr[nt][0] = cB[(nb + g) * LDK + kk + t];
                bfr[nt][1] = cB[(nb + g) * LDK + kk + t + 4];
            }
            #pragma unroll
            for (int mt = 0; mt < 2; mt++)
                #pragma unroll
                for (int nt = 0; nt < 6; nt++)
                    mma_tf32(acc[mt][nt], afr[mt], bfr[nt]);
        }
        __syncthreads();
    }

    // ---- stage P (64 x 192) into smem ----
    float* P = smemf;
    #pragma unroll
    for (int mt = 0; mt < 2; mt++) {
        int r0 = wm * 32 + mt * 16 + g;
        #pragma unroll
        for (int nt = 0; nt < 6; nt++) {
            int c0 = wn * 48 + nt * 8 + 2 * t;
            *reinterpret_cast<float2*>(P + r0 * LDP + c0) =
                make_float2(acc[mt][nt][0], acc[mt][nt][1]);
            *reinterpret_cast<float2*>(P + (r0 + 8) * LDP + c0) =
                make_float2(acc[mt][nt][2], acc[mt][nt][3]);
        }
    }
    __syncthreads();

    // ---- fused elementwise state update (64 rows x 64 ranks) ----
    const float PI_F = 3.14159265358979323846f;
    const int r = tid & 63;
    const float bdt_r = bdt[r];
    const float bph_r = bph[r];
    const float eA_r  = expf(Areal[r]);
    const float Ai_r  = Aimag[r];

    #pragma unroll
    for (int i = 0; i < 16; i++) {
        int idx  = tid + i * 256;              // 4096 = 64*64
        int row  = idx >> 6;
        int grow = m0 + row;

        float zdt   = P[row * LDP + r] + bdt_r;
        float dt    = (zdt > 20.f) ? zdt : log1pf(expf(zdt));
        float zph   = P[row * LDP + 64 + r] + bph_r;
        float phase = tanhf(zph) * PI_F;
        float decay = expf(-dt * eA_r);
        float angle = fmaf(dt, Ai_r, phase);
        float Bv    = P[row * LDP + 128 + r];

        float sn, cs;
        sincosf(angle, &sn, &cs);

        float a_ = sre[(size_t)grow * RANK + r];
        float b_ = sim_[(size_t)grow * RANK + r];

        nre[(size_t)grow * RANK + r] = fmaf(a_ * cs - b_ * sn, decay, Bv);
        nim[(size_t)grow * RANK + r] = (a_ * sn + b_ * cs) * decay;
    }
}

// ---------------------------------------------------------------------------
// Kernel 2 (R1 config, known 43.6us): out = new_re @ W_C^T  (M=16384,N=2048,K=64)
// CTA 256 thr, tile 128 x 128, whole K in smem.
// ---------------------------------------------------------------------------
#define LDK2 68

__global__ void __launch_bounds__(256) out_kernel(
    const float* __restrict__ nre,
    const float* __restrict__ WC,
    float* __restrict__ out)
{
    extern __shared__ float smemf[];
    float* sA = smemf;                  // 128 x LDK2
    float* sB = smemf + 128 * LDK2;     // 128 x LDK2

    const int tid  = threadIdx.x;
    const int wid  = tid >> 5;
    const int lane = tid & 31;
    const int g    = lane >> 2;
    const int t    = lane & 3;
    const int wm   = wid >> 2;          // 0..1 (64 rows each)
    const int wn   = wid & 3;           // 0..3 (32 cols each)
    const int m0   = blockIdx.x * 128;
    const int n0   = blockIdx.y * 128;

    #pragma unroll
    for (int i = 0; i < 8; i++) {
        int idx = tid + i * 256;        // 128 rows * 16 float4
        int row = idx >> 4, c4 = (idx & 15) << 2;
        float4 v = *reinterpret_cast<const float4*>(nre + (size_t)(m0 + row) * RANK + c4);
        float4 w;
        w.x = tf32r(v.x); w.y = tf32r(v.y); w.z = tf32r(v.z); w.w = tf32r(v.w);
        *reinterpret_cast<float4*>(sA + row * LDK2 + c4) = w;

        v = *reinterpret_cast<const float4*>(WC + (size_t)(n0 + row) * RANK + c4);
        w.x = tf32r(v.x); w.y = tf32r(v.y); w.z = tf32r(v.z); w.w = tf32r(v.w);
        *reinterpret_cast<float4*>(sB + row * LDK2 + c4) = w;
    }
    __syncthreads();

    float acc[4][4][4];
    #pragma unroll
    for (int i = 0; i < 4; i++)
        #pragma unroll
        for (int j = 0; j < 4; j++)
            #pragma unroll
            for (int k = 0; k < 4; k++) acc[i][j][k] = 0.f;

    #pragma unroll
    for (int k8 = 0; k8 < 8; k8++) {
        int kk = k8 * 8;
        float afr[4][4], bfr[4][2];
        #pragma unroll
        for (int mt = 0; mt < 4; mt++) {
            int rb0 = wm * 64 + mt * 16;
            afr[mt][0] = sA[(rb0 + g)     * LDK2 + kk + t];
            afr[mt][1] = sA[(rb0 + g + 8) * LDK2 + kk + t];
            afr[mt][2] = sA[(rb0 + g)     * LDK2 + kk + t + 4];
            afr[mt][3] = sA[(rb0 + g + 8) * LDK2 + kk + t + 4];
        }
        #pragma unroll
        for (int nt = 0; nt < 4; nt++) {
            int nb = wn * 32 + nt * 8;
            bfr[nt][0] = sB[(nb + g) * LDK2 + kk + t];
            bfr[nt][1] = sB[(nb + g) * LDK2 + kk + t + 4];
        }
        #pragma unroll
        for (int mt = 0; mt < 4; mt++)
            #pragma unroll
            for (int nt = 0; nt < 4; nt++)
                mma_tf32(acc[mt][nt], afr[mt], bfr[nt]);
    }

    #pragma unroll
    for (int mt = 0; mt < 4; mt++) {
        int row = m0 + wm * 64 + mt * 16 + g;
        #pragma unroll
        for (int nt = 0; nt < 4; nt++) {
            int col = n0 + wn * 32 + nt * 8 + 2 * t;
            *reinterpret_cast<float2*>(out + (size_t)row * DMODEL + col) =
                make_float2(acc[mt][nt][0], acc[mt][nt][1]);
            *reinterpret_cast<float2*>(out + (size_t)(row + 8) * DMODEL + col) =
                make_float2(acc[mt][nt][2], acc[mt][nt][3]);
        }
    }
}

// ---------------------------------------------------------------------------
// launch
// ---------------------------------------------------------------------------
extern "C" void kernel_launch(void* const* d_in, const int* in_sizes, int n_in,
                              void* d_out, int out_size)
{
    const float* x    = (const float*)d_in[0];
    const float* sre  = (const float*)d_in[1];
    const float* sim_ = (const float*)d_in[2];
    const float* Wdt  = (const float*)d_in[3];
    const float* bdt  = (const float*)d_in[4];
    const float* Wph  = (const float*)d_in[5];
    const float* bph  = (const float*)d_in[6];
    const float* WB   = (const float*)d_in[7];
    const float* WC   = (const float*)d_in[8];
    const float* Ar   = (const float*)d_in[9];
    const float* Ai   = (const float*)d_in[10];

    float* out = (float*)d_out;
    float* nre = out + (size_t)BATCH * DMODEL;
    float* nim = nre + (size_t)BATCH * RANK;

    const int smem1 = SMEM1;                              // 73728 B
    const int smem2 = 2 * 128 * LDK2 * sizeof(float);     // 69632 B

    cudaFuncSetAttribute(proj_kernel, cudaFuncAttributeMaxDynamicSharedMemorySize, smem1);
    cudaFuncSetAttribute(out_kernel,  cudaFuncAttributeMaxDynamicSharedMemorySize, smem2);

    proj_kernel<<<BATCH / 64, 256, smem1>>>(x, sre, sim_, Wdt, bdt, Wph, bph, WB,
                                            Ar, Ai, nre, nim);
    out_kernel<<<dim3(BATCH / 128, DMODEL / 128), 256, smem2>>>(nre, WC, out);
}

// round 8
// speedup vs baseline: 1.3071x; 1.2447x over previous
#include <cuda_runtime.h>
#include <cstdint>
#include <math.h>

#define BATCH  16384
#define DMODEL 2048
#define RANK   64
#define NPROJ  192

// ---------------------------------------------------------------------------
// helpers
// ---------------------------------------------------------------------------
__device__ __forceinline__ float tf32r(float v) {
    uint32_t u;
    asm("cvt.rna.tf32.f32 %0, %1;" : "=r"(u) : "f"(v));
    return __uint_as_float(u);
}
__device__ __forceinline__ uint32_t smem_u32(const void* p) {
    uint32_t a;
    asm("{ .reg .u64 t; cvta.to.shared.u64 t, %1; cvt.u32.u64 %0, t; }"
        : "=r"(a) : "l"(p));
    return a;
}

// tf32 m16n8k8: D += A*B  (A,B as uint32 fragment regs from ldmatrix)
__device__ __forceinline__ void mma_tf32(float* d, const uint32_t* A, const uint32_t* B) {
    asm volatile(
        "mma.sync.aligned.m16n8k8.row.col.f32.tf32.tf32.f32 "
        "{%0,%1,%2,%3}, {%4,%5,%6,%7}, {%8,%9}, {%0,%1,%2,%3};\n"
        : "+f"(d[0]), "+f"(d[1]), "+f"(d[2]), "+f"(d[3])
        : "r"(A[0]), "r"(A[1]), "r"(A[2]), "r"(A[3]), "r"(B[0]), "r"(B[1]));
}

__device__ __forceinline__ void ldsm_x4(uint32_t* r, uint32_t addr) {
    asm volatile("ldmatrix.sync.aligned.m8n8.x4.shared.b16 {%0,%1,%2,%3}, [%4];"
                 : "=r"(r[0]), "=r"(r[1]), "=r"(r[2]), "=r"(r[3]) : "r"(addr));
}
__device__ __forceinline__ void ldsm_x2(uint32_t* r, uint32_t addr) {
    asm volatile("ldmatrix.sync.aligned.m8n8.x2.shared.b16 {%0,%1}, [%2];"
                 : "=r"(r[0]), "=r"(r[1]) : "r"(addr));
}

// ---------------------------------------------------------------------------
// Kernel 1: P = x @ [W_dt;W_ph;W_B]^T  (M=16384, N=192, K=2048)
// R1 pipeline (single smem buffer, ldg->compute->sync->sts->sync),
// fragments via ldmatrix. CTA 256 thr, tile 64x192, warp 32x48, grid 256.
// ---------------------------------------------------------------------------
#define LDK   36
#define ASZ   (64  * LDK)
#define BSZ   (192 * LDK)
#define LDP   194
#define NKT   (DMODEL / 32)
#define SMEM1 (64 * LDP * 4)   // 49664 B (>= A+B tiles 36864 B)

__global__ void __launch_bounds__(256, 2) proj_kernel(
    const float* __restrict__ x,
    const float* __restrict__ sre, const float* __restrict__ sim_,
    const float* __restrict__ Wdt, const float* __restrict__ bdt,
    const float* __restrict__ Wph, const float* __restrict__ bph,
    const float* __restrict__ WB,
    const float* __restrict__ Areal, const float* __restrict__ Aimag,
    float* __restrict__ nre, float* __restrict__ nim)
{
    extern __shared__ float smemf[];
    float* sA = smemf;            // 64  x LDK
    float* sB = smemf + ASZ;      // 192 x LDK

    const int tid  = threadIdx.x;
    const int wid  = tid >> 5;
    const int lane = tid & 31;
    const int wm   = wid >> 2;     // 0..1  (32 rows)
    const int wn   = wid & 3;      // 0..3  (48 cols)
    const int m0   = blockIdx.x * 64;

    const uint32_t sbase = smem_u32(smemf);
    const uint32_t aBase = sbase;
    const uint32_t bBase = sbase + ASZ * 4;

    // ldmatrix per-lane byte offsets (loop-invariant)
    const int part = lane >> 3, rA = lane & 7;
    uint32_t aLm[2];
    #pragma unroll
    for (int mt = 0; mt < 2; mt++) {
        int row  = wm * 32 + mt * 16 + (part & 1) * 8 + rA;
        int colf = (part >> 1) * 4;
        aLm[mt] = aBase + (uint32_t)(row * LDK + colf) * 4;
    }
    const int l16 = lane & 15;
    uint32_t bLm[6];
    #pragma unroll
    for (int nt = 0; nt < 6; nt++) {
        int row  = wn * 48 + nt * 8 + (l16 & 7);
        int colf = (l16 >> 3) * 4;
        bLm[nt] = bBase + (uint32_t)(row * LDK + colf) * 4;
    }

    // global-load geometry
    const float* aP[2]; int aOfs[2];
    #pragma unroll
    for (int i = 0; i < 2; i++) {
        int idx = tid + i * 256;
        int row = idx >> 3, c4 = (idx & 7) << 2;
        aP[i]   = x + (size_t)(m0 + row) * DMODEL + c4;
        aOfs[i] = row * LDK + c4;
    }
    const float* bP[6]; int bOfs[6];
    #pragma unroll
    for (int i = 0; i < 6; i++) {
        int idx = tid + i * 256;
        int row = idx >> 3, c4 = (idx & 7) << 2;
        const float* W = (row < 64)  ? (Wdt + (size_t)row * DMODEL)
                       : (row < 128) ? (Wph + (size_t)(row - 64) * DMODEL)
                                     : (WB  + (size_t)(row - 128) * DMODEL);
        bP[i]   = W + c4;
        bOfs[i] = row * LDK + c4;
    }

    float acc[2][6][4];
    #pragma unroll
    for (int i = 0; i < 2; i++)
        #pragma unroll
        for (int j = 0; j < 6; j++)
            #pragma unroll
            for (int k = 0; k < 4; k++) acc[i][j][k] = 0.f;

    float4 ra[2], rb[6];
    auto ldg = [&](int kt) {
        #pragma unroll
        for (int i = 0; i < 2; i++)
            ra[i] = *reinterpret_cast<const float4*>(aP[i] + kt * 32);
        #pragma unroll
        for (int i = 0; i < 6; i++)
            rb[i] = *reinterpret_cast<const float4*>(bP[i] + kt * 32);
    };
    auto sts = [&]() {
        #pragma unroll
        for (int i = 0; i < 2; i++) {
            float4 v = ra[i], w;
            w.x = tf32r(v.x); w.y = tf32r(v.y); w.z = tf32r(v.z); w.w = tf32r(v.w);
            *reinterpret_cast<float4*>(sA + aOfs[i]) = w;
        }
        #pragma unroll
        for (int i = 0; i < 6; i++) {
            float4 v = rb[i], w;
            w.x = tf32r(v.x); w.y = tf32r(v.y); w.z = tf32r(v.z); w.w = tf32r(v.w);
            *reinterpret_cast<float4*>(sB + bOfs[i]) = w;
        }
    };

    // prologue: tile 0 -> smem
    ldg(0); sts();
    __syncthreads();

    for (int kt = 0; kt < NKT; ++kt) {
        if (kt + 1 < NKT) ldg(kt + 1);     // LDG latency hidden under compute

        #pragma unroll
        for (int k8 = 0; k8 < 4; k8++) {
            const uint32_t kB = (uint32_t)k8 * 32;   // 8 floats = 32 bytes
            uint32_t afr[2][4], bfr[6][2];
            #pragma unroll
            for (int mt = 0; mt < 2; mt++) ldsm_x4(afr[mt], aLm[mt] + kB);
            #pragma unroll
            for (int nt = 0; nt < 6; nt++) ldsm_x2(bfr[nt], bLm[nt] + kB);
            #pragma unroll
            for (int mt = 0; mt < 2; mt++)
                #pragma unroll
                for (int nt = 0; nt < 6; nt++)
                    mma_tf32(acc[mt][nt], afr[mt], bfr[nt]);
        }
        __syncthreads();
        if (kt + 1 < NKT) {
            sts();
            __syncthreads();
        }
    }

    // ---- stage P (64 x 192) into smem ----
    const int g = lane >> 2, t = lane & 3;
    float* P = smemf;
    #pragma unroll
    for (int mt = 0; mt < 2; mt++) {
        int r0 = wm * 32 + mt * 16 + g;
        #pragma unroll
        for (int nt = 0; nt < 6; nt++) {
            int c0 = wn * 48 + nt * 8 + 2 * t;
            *reinterpret_cast<float2*>(P + r0 * LDP + c0) =
                make_float2(acc[mt][nt][0], acc[mt][nt][1]);
            *reinterpret_cast<float2*>(P + (r0 + 8) * LDP + c0) =
                make_float2(acc[mt][nt][2], acc[mt][nt][3]);
        }
    }
    __syncthreads();

    // ---- fused elementwise state update (64 rows x 64 ranks) ----
    const float PI_F = 3.14159265358979323846f;
    const int r = tid & 63;
    const float bdt_r = bdt[r];
    const float bph_r = bph[r];
    const float eA_r  = expf(Areal[r]);
    const float Ai_r  = Aimag[r];

    #pragma unroll
    for (int i = 0; i < 16; i++) {
        int idx  = tid + i * 256;
        int row  = idx >> 6;
        int grow = m0 + row;

        float zdt   = P[row * LDP + r] + bdt_r;
        float dt    = (zdt > 20.f) ? zdt : log1pf(expf(zdt));
        float zph   = P[row * LDP + 64 + r] + bph_r;
        float phase = tanhf(zph) * PI_F;
        float decay = expf(-dt * eA_r);
        float angle = fmaf(dt, Ai_r, phase);
        float Bv    = P[row * LDP + 128 + r];

        float sn, cs;
        sincosf(angle, &sn, &cs);

        float a_ = sre[(size_t)grow * RANK + r];
        float b_ = sim_[(size_t)grow * RANK + r];

        nre[(size_t)grow * RANK + r] = fmaf(a_ * cs - b_ * sn, decay, Bv);
        nim[(size_t)grow * RANK + r] = (a_ * sn + b_ * cs) * decay;
    }
}

// ---------------------------------------------------------------------------
// Kernel 2: out = new_re @ W_C^T  (M=16384, N=2048, K=64)
// R1 config (128x128, whole K in smem) + ldmatrix fragment loads.
// ---------------------------------------------------------------------------
#define LDK2 68

__global__ void __launch_bounds__(256) out_kernel(
    const float* __restrict__ nre,
    const float* __restrict__ WC,
    float* __restrict__ out)
{
    extern __shared__ float smemf[];
    float* sA = smemf;                  // 128 x LDK2
    float* sB = smemf + 128 * LDK2;     // 128 x LDK2

    const int tid  = threadIdx.x;
    const int wid  = tid >> 5;
    const int lane = tid & 31;
    const int wm   = wid >> 2;          // 0..1 (64 rows each)
    const int wn   = wid & 3;           // 0..3 (32 cols each)
    const int m0   = blockIdx.x * 128;
    const int n0   = blockIdx.y * 128;

    const uint32_t sbase = smem_u32(smemf);
    const uint32_t aBase = sbase;
    const uint32_t bBase = sbase + 128 * LDK2 * 4;

    const int part = lane >> 3, rA = lane & 7;
    uint32_t aLm[4];
    #pragma unroll
    for (int mt = 0; mt < 4; mt++) {
        int row  = wm * 64 + mt * 16 + (part & 1) * 8 + rA;
        int colf = (part >> 1) * 4;
        aLm[mt] = aBase + (uint32_t)(row * LDK2 + colf) * 4;
    }
    const int l16 = lane & 15;
    uint32_t bLm[4];
    #pragma unroll
    for (int nt = 0; nt < 4; nt++) {
        int row  = wn * 32 + nt * 8 + (l16 & 7);
        int colf = (l16 >> 3) * 4;
        bLm[nt] = bBase + (uint32_t)(row * LDK2 + colf) * 4;
    }

    #pragma unroll
    for (int i = 0; i < 8; i++) {
        int idx = tid + i * 256;        // 128 rows * 16 float4
        int row = idx >> 4, c4 = (idx & 15) << 2;
        float4 v = *reinterpret_cast<const float4*>(nre + (size_t)(m0 + row) * RANK + c4);
        float4 w;
        w.x = tf32r(v.x); w.y = tf32r(v.y); w.z = tf32r(v.z); w.w = tf32r(v.w);
        *reinterpret_cast<float4*>(sA + row * LDK2 + c4) = w;

        v = *reinterpret_cast<const float4*>(WC + (size_t)(n0 + row) * RANK + c4);
        w.x = tf32r(v.x); w.y = tf32r(v.y); w.z = tf32r(v.z); w.w = tf32r(v.w);
        *reinterpret_cast<float4*>(sB + row * LDK2 + c4) = w;
    }
    __syncthreads();

    float acc[4][4][4];
    #pragma unroll
    for (int i = 0; i < 4; i++)
        #pragma unroll
        for (int j = 0; j < 4; j++)
            #pragma unroll
            for (int k = 0; k < 4; k++) acc[i][j][k] = 0.f;

    #pragma unroll
    for (int k8 = 0; k8 < 8; k8++) {
        const uint32_t kB = (uint32_t)k8 * 32;
        uint32_t afr[4][4], bfr[4][2];
        #pragma unroll
        for (int mt = 0; mt < 4; mt++) ldsm_x4(afr[mt], aLm[mt] + kB);
        #pragma unroll
        for (int nt = 0; nt < 4; nt++) ldsm_x2(bfr[nt], bLm[nt] + kB);
        #pragma unroll
        for (int mt = 0; mt < 4; mt++)
            #pragma unroll
            for (int nt = 0; nt < 4; nt++)
                mma_tf32(acc[mt][nt], afr[mt], bfr[nt]);
    }

    const int g = lane >> 2, t = lane & 3;
    #pragma unroll
    for (int mt = 0; mt < 4; mt++) {
        int row = m0 + wm * 64 + mt * 16 + g;
        #pragma unroll
        for (int nt = 0; nt < 4; nt++) {
            int col = n0 + wn * 32 + nt * 8 + 2 * t;
            *reinterpret_cast<float2*>(out + (size_t)row * DMODEL + col) =
                make_float2(acc[mt][nt][0], acc[mt][nt][1]);
            *reinterpret_cast<float2*>(out + (size_t)(row + 8) * DMODEL + col) =
                make_float2(acc[mt][nt][2], acc[mt][nt][3]);
        }
    }
}

// ---------------------------------------------------------------------------
// launch
// ---------------------------------------------------------------------------
extern "C" void kernel_launch(void* const* d_in, const int* in_sizes, int n_in,
                              void* d_out, int out_size)
{
    const float* x    = (const float*)d_in[0];
    const float* sre  = (const float*)d_in[1];
    const float* sim_ = (const float*)d_in[2];
    const float* Wdt  = (const float*)d_in[3];
    const float* bdt  = (const float*)d_in[4];
    const float* Wph  = (const float*)d_in[5];
    const float* bph  = (const float*)d_in[6];
    const float* WB   = (const float*)d_in[7];
    const float* WC   = (const float*)d_in[8];
    const float* Ar   = (const float*)d_in[9];
    const float* Ai   = (const float*)d_in[10];

    float* out = (float*)d_out;
    float* nre = out + (size_t)BATCH * DMODEL;
    float* nim = nre + (size_t)BATCH * RANK;

    const int smem1 = SMEM1;                              // 49664 B
    const int smem2 = 2 * 128 * LDK2 * sizeof(float);     // 69632 B

    cudaFuncSetAttribute(proj_kernel, cudaFuncAttributeMaxDynamicSharedMemorySize, smem1);
    cudaFuncSetAttribute(out_kernel,  cudaFuncAttributeMaxDynamicSharedMemorySize, smem2);

    proj_kernel<<<BATCH / 64, 256, smem1>>>(x, sre, sim_, Wdt, bdt, Wph, bph, WB,
                                            Ar, Ai, nre, nim);
    out_kernel<<<dim3(BATCH / 128, DMODEL / 128), 256, smem2>>>(nre, WC, out);
}

// round 10
// speedup vs baseline: 1.5297x; 1.1703x over previous
#include <cuda_runtime.h>
#include <cuda_fp16.h>
#include <cstdint>
#include <math.h>

#define BATCH  16384
#define DMODEL 2048
#define RANK   64
#define NPROJ  192

// ---------------------------------------------------------------------------
// helpers
// ---------------------------------------------------------------------------
__device__ __forceinline__ uint32_t smem_u32(const void* p) {
    uint32_t a;
    asm("{ .reg .u64 t; cvta.to.shared.u64 t, %1; cvt.u32.u64 %0, t; }"
        : "=r"(a) : "l"(p));
    return a;
}

// fp16 m16n8k16: D(f32) += A(f16)*B(f16)
__device__ __forceinline__ void mma_f16(float* d, const uint32_t* A, const uint32_t* B) {
    asm volatile(
        "mma.sync.aligned.m16n8k16.row.col.f32.f16.f16.f32 "
        "{%0,%1,%2,%3}, {%4,%5,%6,%7}, {%8,%9}, {%0,%1,%2,%3};\n"
        : "+f"(d[0]), "+f"(d[1]), "+f"(d[2]), "+f"(d[3])
        : "r"(A[0]), "r"(A[1]), "r"(A[2]), "r"(A[3]), "r"(B[0]), "r"(B[1]));
}

__device__ __forceinline__ void ldsm_x4(uint32_t* r, uint32_t addr) {
    asm volatile("ldmatrix.sync.aligned.m8n8.x4.shared.b16 {%0,%1,%2,%3}, [%4];"
                 : "=r"(r[0]), "=r"(r[1]), "=r"(r[2]), "=r"(r[3]) : "r"(addr));
}
__device__ __forceinline__ void ldsm_x2(uint32_t* r, uint32_t addr) {
    asm volatile("ldmatrix.sync.aligned.m8n8.x2.shared.b16 {%0,%1}, [%2];"
                 : "=r"(r[0]), "=r"(r[1]) : "r"(addr));
}

// pack float4 -> two half2 (8 bytes)
__device__ __forceinline__ uint2 pack_h4(float4 v) {
    __half2 h0 = __floats2half2_rn(v.x, v.y);
    __half2 h1 = __floats2half2_rn(v.z, v.w);
    uint2 u;
    u.x = *reinterpret_cast<uint32_t*>(&h0);
    u.y = *reinterpret_cast<uint32_t*>(&h1);
    return u;
}

// ---------------------------------------------------------------------------
// Kernel 1: P = x @ [W_dt;W_ph;W_B]^T  (M=16384, N=192, K=2048)  fp16 MMA
// CTA 256 thr, tile 64x192, BK=32 (2 x k16). warp 32x48, grid 256.
// Single-buffer pipeline (R1-proven): ldg -> compute -> sync -> sts -> sync.
// ---------------------------------------------------------------------------
#define LDKH  40                     // halves per smem row (80B, conflict-free)
#define ASZH  (64  * LDKH)           // halves in A tile
#define BSZH  (192 * LDKH)
#define LDP   194
#define NKT   (DMODEL / 32)
#define SMEM1 (64 * LDP * 4)         // 49664 B  (tiles need (ASZH+BSZH)*2 = 20480 B)

__global__ void __launch_bounds__(256, 2) proj_kernel(
    const float* __restrict__ x,
    const float* __restrict__ sre, const float* __restrict__ sim_,
    const float* __restrict__ Wdt, const float* __restrict__ bdt,
    const float* __restrict__ Wph, const float* __restrict__ bph,
    const float* __restrict__ WB,
    const float* __restrict__ Areal, const float* __restrict__ Aimag,
    float* __restrict__ nre, float* __restrict__ nim)
{
    extern __shared__ float smemf[];
    __half* sA = reinterpret_cast<__half*>(smemf);          // 64  x LDKH
    __half* sB = sA + ASZH;                                 // 192 x LDKH

    const int tid  = threadIdx.x;
    const int wid  = tid >> 5;
    const int lane = tid & 31;
    const int wm   = wid >> 2;     // 0..1  (32 rows)
    const int wn   = wid & 3;      // 0..3  (48 cols)
    const int m0   = blockIdx.x * 64;

    const uint32_t aBase = smem_u32(sA);
    const uint32_t bBase = smem_u32(sB);

    // ldmatrix per-lane byte addresses (loop-invariant)
    const int part = lane >> 3, rA = lane & 7;
    uint32_t aLm[2];
    #pragma unroll
    for (int mt = 0; mt < 2; mt++) {
        int row  = wm * 32 + mt * 16 + (part & 1) * 8 + rA;
        int colh = (part >> 1) * 8;          // 0 or 8 halves (=16B)
        aLm[mt] = aBase + (uint32_t)(row * LDKH + colh) * 2;
    }
    const int l16 = lane & 15;
    uint32_t bLm[6];
    #pragma unroll
    for (int nt = 0; nt < 6; nt++) {
        int row  = wn * 48 + nt * 8 + (l16 & 7);
        int colh = (l16 >> 3) * 8;
        bLm[nt] = bBase + (uint32_t)(row * LDKH + colh) * 2;
    }

    // global-load geometry: A 2 float4/thread, B 6 float4/thread
    const float* aP[2]; int aOfs[2];
    #pragma unroll
    for (int i = 0; i < 2; i++) {
        int idx = tid + i * 256;
        int row = idx >> 3, c4 = (idx & 7) << 2;
        aP[i]   = x + (size_t)(m0 + row) * DMODEL + c4;
        aOfs[i] = row * LDKH + c4;           // half index; c4 mult of 4 -> 8B aligned
    }
    const float* bP[6]; int bOfs[6];
    #pragma unroll
    for (int i = 0; i < 6; i++) {
        int idx = tid + i * 256;
        int row = idx >> 3, c4 = (idx & 7) << 2;
        const float* W = (row < 64)  ? (Wdt + (size_t)row * DMODEL)
                       : (row < 128) ? (Wph + (size_t)(row - 64) * DMODEL)
                                     : (WB  + (size_t)(row - 128) * DMODEL);
        bP[i]   = W + c4;
        bOfs[i] = row * LDKH + c4;
    }

    float acc[2][6][4];
    #pragma unroll
    for (int i = 0; i < 2; i++)
        #pragma unroll
        for (int j = 0; j < 6; j++)
            #pragma unroll
            for (int k = 0; k < 4; k++) acc[i][j][k] = 0.f;

    float4 ra[2], rb[6];
    auto ldg = [&](int kt) {
        #pragma unroll
        for (int i = 0; i < 2; i++)
            ra[i] = *reinterpret_cast<const float4*>(aP[i] + kt * 32);
        #pragma unroll
        for (int i = 0; i < 6; i++)
            rb[i] = *reinterpret_cast<const float4*>(bP[i] + kt * 32);
    };
    auto sts = [&]() {
        #pragma unroll
        for (int i = 0; i < 2; i++)
            *reinterpret_cast<uint2*>(sA + aOfs[i]) = pack_h4(ra[i]);
        #pragma unroll
        for (int i = 0; i < 6; i++)
            *reinterpret_cast<uint2*>(sB + bOfs[i]) = pack_h4(rb[i]);
    };

    // prologue
    ldg(0); sts();
    __syncthreads();

    for (int kt = 0; kt < NKT; ++kt) {
        if (kt + 1 < NKT) ldg(kt + 1);

        #pragma unroll
        for (int k16 = 0; k16 < 2; k16++) {
            const uint32_t kB = (uint32_t)k16 * 32;   // 16 halves = 32 bytes
            uint32_t afr[2][4], bfr[6][2];
            #pragma unroll
            for (int mt = 0; mt < 2; mt++) ldsm_x4(afr[mt], aLm[mt] + kB);
            #pragma unroll
            for (int nt = 0; nt < 6; nt++) ldsm_x2(bfr[nt], bLm[nt] + kB);
            #pragma unroll
            for (int mt = 0; mt < 2; mt++)
                #pragma unroll
                for (int nt = 0; nt < 6; nt++)
                    mma_f16(acc[mt][nt], afr[mt], bfr[nt]);
        }
        __syncthreads();
        if (kt + 1 < NKT) {
            sts();
            __syncthreads();
        }
    }

    // ---- stage P (64 x 192) into smem (f32) ----
    const int g = lane >> 2, t = lane & 3;
    float* P = smemf;
    #pragma unroll
    for (int mt = 0; mt < 2; mt++) {
        int r0 = wm * 32 + mt * 16 + g;
        #pragma unroll
        for (int nt = 0; nt < 6; nt++) {
            int c0 = wn * 48 + nt * 8 + 2 * t;
            *reinterpret_cast<float2*>(P + r0 * LDP + c0) =
                make_float2(acc[mt][nt][0], acc[mt][nt][1]);
            *reinterpret_cast<float2*>(P + (r0 + 8) * LDP + c0) =
                make_float2(acc[mt][nt][2], acc[mt][nt][3]);
        }
    }
    __syncthreads();

    // ---- fused elementwise state update (64 rows x 64 ranks) ----
    const float PI_F = 3.14159265358979323846f;
    const int r = tid & 63;
    const float bdt_r = bdt[r];
    const float bph_r = bph[r];
    const float eA_r  = expf(Areal[r]);
    const float Ai_r  = Aimag[r];

    #pragma unroll
    for (int i = 0; i < 16; i++) {
        int idx  = tid + i * 256;
        int row  = idx >> 6;
        int grow = m0 + row;

        float zdt   = P[row * LDP + r] + bdt_r;
        float dt    = (zdt > 20.f) ? zdt : log1pf(expf(zdt));
        float zph   = P[row * LDP + 64 + r] + bph_r;
        float phase = tanhf(zph) * PI_F;
        float decay = expf(-dt * eA_r);
        float angle = fmaf(dt, Ai_r, phase);
        float Bv    = P[row * LDP + 128 + r];

        float sn, cs;
        sincosf(angle, &sn, &cs);

        float a_ = sre[(size_t)grow * RANK + r];
        float b_ = sim_[(size_t)grow * RANK + r];

        nre[(size_t)grow * RANK + r] = fmaf(a_ * cs - b_ * sn, decay, Bv);
        nim[(size_t)grow * RANK + r] = (a_ * sn + b_ * cs) * decay;
    }
}

// ---------------------------------------------------------------------------
// Kernel 2: out = new_re @ W_C^T  (M=16384, N=2048, K=64)  fp16 MMA
// CTA 256 thr, tile 128x128, whole K in smem. 2 CTAs/SM enforced.
// ---------------------------------------------------------------------------
#define LDK2H 72    // halves per row (144 B) -> conflict-free ldmatrix

__global__ void __launch_bounds__(256, 2) out_kernel(
    const float* __restrict__ nre,
    const float* __restrict__ WC,
    float* __restrict__ out)
{
    extern __shared__ float smemf[];
    __half* sA = reinterpret_cast<__half*>(smemf);          // 128 x LDK2H
    __half* sB = sA + 128 * LDK2H;                          // 128 x LDK2H

    const int tid  = threadIdx.x;
    const int wid  = tid >> 5;
    const int lane = tid & 31;
    const int wm   = wid >> 2;          // 0..1 (64 rows each)
    const int wn   = wid & 3;           // 0..3 (32 cols each)
    const int m0   = blockIdx.x * 128;
    const int n0   = blockIdx.y * 128;

    const uint32_t aBase = smem_u32(sA);
    const uint32_t bBase = smem_u32(sB);

    const int part = lane >> 3, rA = lane & 7;
    uint32_t aLm[4];
    #pragma unroll
    for (int mt = 0; mt < 4; mt++) {
        int row  = wm * 64 + mt * 16 + (part & 1) * 8 + rA;
        int colh = (part >> 1) * 8;
        aLm[mt] = aBase + (uint32_t)(row * LDK2H + colh) * 2;
    }
    const int l16 = lane & 15;
    uint32_t bLm[4];
    #pragma unroll
    for (int nt = 0; nt < 4; nt++) {
        int row  = wn * 32 + nt * 8 + (l16 & 7);
        int colh = (l16 >> 3) * 8;
        bLm[nt] = bBase + (uint32_t)(row * LDK2H + colh) * 2;
    }

    #pragma unroll
    for (int i = 0; i < 8; i++) {
        int idx = tid + i * 256;        // 128 rows * 16 float4
        int row = idx >> 4, c4 = (idx & 15) << 2;
        float4 v = *reinterpret_cast<const float4*>(nre + (size_t)(m0 + row) * RANK + c4);
        *reinterpret_cast<uint2*>(sA + row * LDK2H + c4) = pack_h4(v);

        v = *reinterpret_cast<const float4*>(WC + (size_t)(n0 + row) * RANK + c4);
        *reinterpret_cast<uint2*>(sB + row * LDK2H + c4) = pack_h4(v);
    }
    __syncthreads();

    float acc[4][4][4];
    #pragma unroll
    for (int i = 0; i < 4; i++)
        #pragma unroll
        for (int j = 0; j < 4; j++)
            #pragma unroll
            for (int k = 0; k < 4; k++) acc[i][j][k] = 0.f;

    #pragma unroll
    for (int k16 = 0; k16 < 4; k16++) {
        const uint32_t kB = (uint32_t)k16 * 32;    // 16 halves = 32 B
        uint32_t afr[4][4], bfr[4][2];
        #pragma unroll
        for (int mt = 0; mt < 4; mt++) ldsm_x4(afr[mt], aLm[mt] + kB);
        #pragma unroll
        for (int nt = 0; nt < 4; nt++) ldsm_x2(bfr[nt], bLm[nt] + kB);
        #pragma unroll
        for (int mt = 0; mt < 4; mt++)
            #pragma unroll
            for (int nt = 0; nt < 4; nt++)
                mma_f16(acc[mt][nt], afr[mt], bfr[nt]);
    }

    const int g = lane >> 2, t = lane & 3;
    #pragma unroll
    for (int mt = 0; mt < 4; mt++) {
        int row = m0 + wm * 64 + mt * 16 + g;
        #pragma unroll
        for (int nt = 0; nt < 4; nt++) {
            int col = n0 + wn * 32 + nt * 8 + 2 * t;
            *reinterpret_cast<float2*>(out + (size_t)row * DMODEL + col) =
                make_float2(acc[mt][nt][0], acc[mt][nt][1]);
            *reinterpret_cast<float2*>(out + (size_t)(row + 8) * DMODEL + col) =
                make_float2(acc[mt][nt][2], acc[mt][nt][3]);
        }
    }
}

// ---------------------------------------------------------------------------
// launch
// ---------------------------------------------------------------------------
extern "C" void kernel_launch(void* const* d_in, const int* in_sizes, int n_in,
                              void* d_out, int out_size)
{
    const float* x    = (const float*)d_in[0];
    const float* sre  = (const float*)d_in[1];
    const float* sim_ = (const float*)d_in[2];
    const float* Wdt  = (const float*)d_in[3];
    const float* bdt  = (const float*)d_in[4];
    const float* Wph  = (const float*)d_in[5];
    const float* bph  = (const float*)d_in[6];
    const float* WB   = (const float*)d_in[7];
    const float* WC   = (const float*)d_in[8];
    const float* Ar   = (const float*)d_in[9];
    const float* Ai   = (const float*)d_in[10];

    float* out = (float*)d_out;
    float* nre = out + (size_t)BATCH * DMODEL;
    float* nim = nre + (size_t)BATCH * RANK;

    const int smem1 = SMEM1;                           // 49664 B
    const int smem2 = 2 * 128 * LDK2H * 2;             // 36864 B

    cudaFuncSetAttribute(proj_kernel, cudaFuncAttributeMaxDynamicSharedMemorySize, smem1);
    cudaFuncSetAttribute(out_kernel,  cudaFuncAttributeMaxDynamicSharedMemorySize, smem2);

    proj_kernel<<<BATCH / 64, 256, smem1>>>(x, sre, sim_, Wdt, bdt, Wph, bph, WB,
                                            Ar, Ai, nre, nim);
    out_kernel<<<dim3(BATCH / 128, DMODEL / 128), 256, smem2>>>(nre, WC, out);
}

// round 11
// speedup vs baseline: 1.8025x; 1.1783x over previous
#include <cuda_runtime.h>
#include <cuda_fp16.h>
#include <cstdint>
#include <math.h>

#define BATCH  16384
#define DMODEL 2048
#define RANK   64
#define NPROJ  192

// fp16 weight / activation mirrors (static scratch; no allocation)
__device__ __half d_Wh[NPROJ * DMODEL];      // concat [Wdt;Wph;WB], 768 KB
__device__ __half d_WCh[DMODEL * RANK];      // 256 KB
__device__ __half d_nreh[(size_t)BATCH * RANK];  // 2 MB

// ---------------------------------------------------------------------------
// helpers
// ---------------------------------------------------------------------------
__device__ __forceinline__ uint32_t smem_u32(const void* p) {
    uint32_t a;
    asm("{ .reg .u64 t; cvta.to.shared.u64 t, %1; cvt.u32.u64 %0, t; }"
        : "=r"(a) : "l"(p));
    return a;
}
__device__ __forceinline__ void mma_f16(float* d, const uint32_t* A, const uint32_t* B) {
    asm volatile(
        "mma.sync.aligned.m16n8k16.row.col.f32.f16.f16.f32 "
        "{%0,%1,%2,%3}, {%4,%5,%6,%7}, {%8,%9}, {%0,%1,%2,%3};\n"
        : "+f"(d[0]), "+f"(d[1]), "+f"(d[2]), "+f"(d[3])
        : "r"(A[0]), "r"(A[1]), "r"(A[2]), "r"(A[3]), "r"(B[0]), "r"(B[1]));
}
__device__ __forceinline__ void ldsm_x4(uint32_t* r, uint32_t addr) {
    asm volatile("ldmatrix.sync.aligned.m8n8.x4.shared.b16 {%0,%1,%2,%3}, [%4];"
                 : "=r"(r[0]), "=r"(r[1]), "=r"(r[2]), "=r"(r[3]) : "r"(addr));
}
__device__ __forceinline__ void ldsm_x2(uint32_t* r, uint32_t addr) {
    asm volatile("ldmatrix.sync.aligned.m8n8.x2.shared.b16 {%0,%1}, [%2];"
                 : "=r"(r[0]), "=r"(r[1]) : "r"(addr));
}
__device__ __forceinline__ uint2 pack_h4(float4 v) {
    __half2 h0 = __floats2half2_rn(v.x, v.y);
    __half2 h1 = __floats2half2_rn(v.z, v.w);
    uint2 u;
    u.x = *reinterpret_cast<uint32_t*>(&h0);
    u.y = *reinterpret_cast<uint32_t*>(&h1);
    return u;
}
__device__ __forceinline__ void cp16(uint32_t saddr, const void* g) {
    asm volatile("cp.async.cg.shared.global [%0], [%1], 16;" :: "r"(saddr), "l"(g));
}
#define CP_COMMIT() asm volatile("cp.async.commit_group;" ::: "memory")
#define CP_WAIT1()  asm volatile("cp.async.wait_group 1;"  ::: "memory")
#define CP_WAIT0()  asm volatile("cp.async.wait_group 0;"  ::: "memory")

// ---------------------------------------------------------------------------
// Kernel 0: f32 -> f16 weight conversion (runs each launch; ~3us)
// ---------------------------------------------------------------------------
__global__ void __launch_bounds__(256) convert_weights(
    const float* __restrict__ Wdt, const float* __restrict__ Wph,
    const float* __restrict__ WB,  const float* __restrict__ WC)
{
    int tid = blockIdx.x * 256 + threadIdx.x;
    if (tid < NPROJ * DMODEL / 4) {            // 98304 float4
        int row = tid >> 9;                    // 512 float4 per row
        int c4  = (tid & 511) << 2;
        const float* src = (row < 64)  ? (Wdt + (size_t)row * DMODEL)
                         : (row < 128) ? (Wph + (size_t)(row - 64) * DMODEL)
                                       : (WB  + (size_t)(row - 128) * DMODEL);
        float4 v = *reinterpret_cast<const float4*>(src + c4);
        *reinterpret_cast<uint2*>(d_Wh + (size_t)row * DMODEL + c4) = pack_h4(v);
    }
    if (tid < DMODEL * RANK / 4) {             // 32768 float4
        float4 v = *reinterpret_cast<const float4*>(WC + (size_t)tid * 4);
        *reinterpret_cast<uint2*>(d_WCh + (size_t)tid * 4) = pack_h4(v);
    }
}

// ---------------------------------------------------------------------------
// Kernel 1: P = x @ Wcat^T  (M=16384, N=192, K=2048)  fp16 MMA
// CTA 256 thr, tile 64x192, BK=32. B via cp.async (triple buffer),
// A via ldg+pack (double buffer). ONE barrier per K-tile.
// ---------------------------------------------------------------------------
#define LDKH  40                       // halves per smem row (80 B)
#define ABUF  (64 * LDKH)              // 2560 halves = 5120 B
#define BBUFB 15360                    // bytes per B buffer (192*40*2)
#define A0OFF 0
#define A1OFF 5120
#define B0OFF 10240
#define LDP   194
#define NKT   (DMODEL / 32)
#define SMEM1 56320                    // B2 ends at 56320; P stage 49664 fits

__global__ void __launch_bounds__(256, 2) proj_kernel(
    const float* __restrict__ x,
    const float* __restrict__ sre, const float* __restrict__ sim_,
    const float* __restrict__ bdt, const float* __restrict__ bph,
    const float* __restrict__ Areal, const float* __restrict__ Aimag,
    float* __restrict__ nre, float* __restrict__ nim)
{
    extern __shared__ float smemf[];
    __half* smh = reinterpret_cast<__half*>(smemf);
    const uint32_t sbase = smem_u32(smemf);

    const int tid  = threadIdx.x;
    const int wid  = tid >> 5;
    const int lane = tid & 31;
    const int wm   = wid >> 2;     // 0..1  (32 rows)
    const int wn   = wid & 3;      // 0..3  (48 cols)
    const int m0   = blockIdx.x * 64;

    // ldmatrix lane addresses (buffer-0 based)
    const int part = lane >> 3, rA = lane & 7;
    uint32_t aLm[2];
    #pragma unroll
    for (int mt = 0; mt < 2; mt++) {
        int row  = wm * 32 + mt * 16 + (part & 1) * 8 + rA;
        int colh = (part >> 1) * 8;
        aLm[mt] = sbase + A0OFF + (uint32_t)(row * LDKH + colh) * 2;
    }
    const int l16 = lane & 15;
    uint32_t bLm[6];
    #pragma unroll
    for (int nt = 0; nt < 6; nt++) {
        int row  = wn * 48 + nt * 8 + (l16 & 7);
        int colh = (l16 >> 3) * 8;
        bLm[nt] = sbase + B0OFF + (uint32_t)(row * LDKH + colh) * 2;
    }

    // A (x, f32) load geometry: 2 float4 / thread
    const float* aP[2]; int aOfs[2];
    #pragma unroll
    for (int i = 0; i < 2; i++) {
        int idx = tid + i * 256;
        int row = idx >> 3, c4 = (idx & 7) << 2;
        aP[i]   = x + (size_t)(m0 + row) * DMODEL + c4;
        aOfs[i] = row * LDKH + c4;
    }
    // B (Wh, fp16) cp.async geometry: 3 x 16B / thread
    const __half* bG[3]; uint32_t bSts[3];
    #pragma unroll
    for (int i = 0; i < 3; i++) {
        int c   = tid + i * 256;           // 768 chunks
        int row = c >> 2, ch = c & 3;
        bG[i]   = d_Wh + (size_t)row * DMODEL + ch * 8;
        bSts[i] = sbase + B0OFF + (uint32_t)(row * LDKH + ch * 8) * 2;
    }

    float acc[2][6][4];
    #pragma unroll
    for (int i = 0; i < 2; i++)
        #pragma unroll
        for (int j = 0; j < 6; j++)
            #pragma unroll
            for (int k = 0; k < 4; k++) acc[i][j][k] = 0.f;

    float4 ra[2];
    auto ldgA = [&](int kt) {
        #pragma unroll
        for (int i = 0; i < 2; i++)
            ra[i] = *reinterpret_cast<const float4*>(aP[i] + kt * 32);
    };
    auto stsA = [&](int ab) {
        __half* dst = smh + (ab ? A1OFF / 2 : 0);
        #pragma unroll
        for (int i = 0; i < 2; i++)
            *reinterpret_cast<uint2*>(dst + aOfs[i]) = pack_h4(ra[i]);
    };
    auto cpB = [&](int kt, int b3) {
        const uint32_t so = (uint32_t)b3 * BBUFB;
        #pragma unroll
        for (int i = 0; i < 3; i++)
            cp16(bSts[i] + so, bG[i] + kt * 32);
        CP_COMMIT();
    };

    // ---- prologue ----
    cpB(0, 0);                // group: B(0)
    cpB(1, 1);                // group: B(1)
    ldgA(0); stsA(0);
    ldgA(1);                  // regs hold A(1)
    CP_WAIT1();               // B(0) arrived (this thread)
    __syncthreads();          // all threads -> B(0), A(0) visible

    int cur3 = 0;
    for (int kt = 0; kt < NKT; ++kt) {
        const int ab = kt & 1;
        // ---- compute tile kt ----
        const uint32_t aOffB = ab ? (uint32_t)A1OFF : 0u;
        const uint32_t bOffB = (uint32_t)cur3 * BBUFB;
        #pragma unroll
        for (int k16 = 0; k16 < 2; k16++) {
            const uint32_t kB = (uint32_t)k16 * 32;
            uint32_t afr[2][4], bfr[6][2];
            #pragma unroll
            for (int mt = 0; mt < 2; mt++) ldsm_x4(afr[mt], aLm[mt] + aOffB + kB);
            #pragma unroll
            for (int nt = 0; nt < 6; nt++) ldsm_x2(bfr[nt], bLm[nt] + bOffB + kB);
            #pragma unroll
            for (int mt = 0; mt < 2; mt++)
                #pragma unroll
                for (int nt = 0; nt < 6; nt++)
                    mma_f16(acc[mt][nt], afr[mt], bfr[nt]);
        }

        if (kt + 1 < NKT) {
            stsA(ab ^ 1);                         // A(kt+1) -> other A buffer
            if (kt + 2 < NKT) {
                int nxt = cur3 + 2; if (nxt >= 3) nxt -= 3;
                cpB(kt + 2, nxt);                 // safe: last read ended at kt-1
                ldgA(kt + 2);
                CP_WAIT1();                       // B(kt+1) arrived
            } else {
                CP_WAIT0();
            }
            __syncthreads();                      // single barrier per iter
        }
        cur3 = (cur3 + 1 == 3) ? 0 : cur3 + 1;
    }
    __syncthreads();   // protect smem reuse below

    // ---- stage P (64 x 192) into smem (f32) ----
    const int g = lane >> 2, t = lane & 3;
    float* P = smemf;
    #pragma unroll
    for (int mt = 0; mt < 2; mt++) {
        int r0 = wm * 32 + mt * 16 + g;
        #pragma unroll
        for (int nt = 0; nt < 6; nt++) {
            int c0 = wn * 48 + nt * 8 + 2 * t;
            *reinterpret_cast<float2*>(P + r0 * LDP + c0) =
                make_float2(acc[mt][nt][0], acc[mt][nt][1]);
            *reinterpret_cast<float2*>(P + (r0 + 8) * LDP + c0) =
                make_float2(acc[mt][nt][2], acc[mt][nt][3]);
        }
    }
    __syncthreads();

    // ---- fused elementwise state update ----
    const float PI_F = 3.14159265358979323846f;
    const int r = tid & 63;
    const float bdt_r = bdt[r];
    const float bph_r = bph[r];
    const float eA_r  = expf(Areal[r]);
    const float Ai_r  = Aimag[r];

    #pragma unroll
    for (int i = 0; i < 16; i++) {
        int idx  = tid + i * 256;
        int row  = idx >> 6;
        int grow = m0 + row;

        float zdt   = P[row * LDP + r] + bdt_r;
        float dt    = (zdt > 20.f) ? zdt : log1pf(expf(zdt));
        float zph   = P[row * LDP + 64 + r] + bph_r;
        float phase = tanhf(zph) * PI_F;
        float decay = expf(-dt * eA_r);
        float angle = fmaf(dt, Ai_r, phase);
        float Bv    = P[row * LDP + 128 + r];

        float sn, cs;
        sincosf(angle, &sn, &cs);

        float a_ = sre[(size_t)grow * RANK + r];
        float b_ = sim_[(size_t)grow * RANK + r];

        float vre = fmaf(a_ * cs - b_ * sn, decay, Bv);
        nre[(size_t)grow * RANK + r]   = vre;
        d_nreh[(size_t)grow * RANK + r] = __float2half(vre);
        nim[(size_t)grow * RANK + r]   = (a_ * sn + b_ * cs) * decay;
    }
}

// ---------------------------------------------------------------------------
// Kernel 2: out = new_re @ W_C^T  (fp16 inputs via cp.async, f32 out)
// CTA 256 thr, tile 128x128, whole K=64 in smem.
// ---------------------------------------------------------------------------
#define LDK2H 72
#define OUT_BOFF (128 * LDK2H * 2)     // 18432 B

__global__ void __launch_bounds__(256, 2) out_kernel(float* __restrict__ out)
{
    extern __shared__ float smemf[];
    const uint32_t sbase = smem_u32(smemf);

    const int tid  = threadIdx.x;
    const int wid  = tid >> 5;
    const int lane = tid & 31;
    const int wm   = wid >> 2;          // 0..1 (64 rows)
    const int wn   = wid & 3;           // 0..3 (32 cols)
    const int m0   = blockIdx.x * 128;
    const int n0   = blockIdx.y * 128;

    // cp.async prologue: A (nreh) + B (WCh), 4 chunks each / thread
    #pragma unroll
    for (int i = 0; i < 4; i++) {
        int c   = tid + i * 256;        // 1024 chunks
        int row = c >> 3, ch = c & 7;
        cp16(sbase + (uint32_t)(row * LDK2H + ch * 8) * 2,
             d_nreh + (size_t)(m0 + row) * RANK + ch * 8);
        cp16(sbase + OUT_BOFF + (uint32_t)(row * LDK2H + ch * 8) * 2,
             d_WCh + (size_t)(n0 + row) * RANK + ch * 8);
    }
    CP_COMMIT();

    const int part = lane >> 3, rA = lane & 7;
    uint32_t aLm[4];
    #pragma unroll
    for (int mt = 0; mt < 4; mt++) {
        int row  = wm * 64 + mt * 16 + (part & 1) * 8 + rA;
        int colh = (part >> 1) * 8;
        aLm[mt] = sbase + (uint32_t)(row * LDK2H + colh) * 2;
    }
    const int l16 = lane & 15;
    uint32_t bLm[4];
    #pragma unroll
    for (int nt = 0; nt < 4; nt++) {
        int row  = wn * 32 + nt * 8 + (l16 & 7);
        int colh = (l16 >> 3) * 8;
        bLm[nt] = sbase + OUT_BOFF + (uint32_t)(row * LDK2H + colh) * 2;
    }

    float acc[4][4][4];
    #pragma unroll
    for (int i = 0; i < 4; i++)
        #pragma unroll
        for (int j = 0; j < 4; j++)
            #pragma unroll
            for (int k = 0; k < 4; k++) acc[i][j][k] = 0.f;

    CP_WAIT0();
    __syncthreads();

    #pragma unroll
    for (int k16 = 0; k16 < 4; k16++) {
        const uint32_t kB = (uint32_t)k16 * 32;
        uint32_t afr[4][4], bfr[4][2];
        #pragma unroll
        for (int mt = 0; mt < 4; mt++) ldsm_x4(afr[mt], aLm[mt] + kB);
        #pragma unroll
        for (int nt = 0; nt < 4; nt++) ldsm_x2(bfr[nt], bLm[nt] + kB);
        #pragma unroll
        for (int mt = 0; mt < 4; mt++)
            #pragma unroll
            for (int nt = 0; nt < 4; nt++)
                mma_f16(acc[mt][nt], afr[mt], bfr[nt]);
    }

    const int g = lane >> 2, t = lane & 3;
    #pragma unroll
    for (int mt = 0; mt < 4; mt++) {
        int row = m0 + wm * 64 + mt * 16 + g;
        #pragma unroll
        for (int nt = 0; nt < 4; nt++) {
            int col = n0 + wn * 32 + nt * 8 + 2 * t;
            *reinterpret_cast<float2*>(out + (size_t)row * DMODEL + col) =
                make_float2(acc[mt][nt][0], acc[mt][nt][1]);
            *reinterpret_cast<float2*>(out + (size_t)(row + 8) * DMODEL + col) =
                make_float2(acc[mt][nt][2], acc[mt][nt][3]);
        }
    }
}

// ---------------------------------------------------------------------------
// launch
// ---------------------------------------------------------------------------
extern "C" void kernel_launch(void* const* d_in, const int* in_sizes, int n_in,
                              void* d_out, int out_size)
{
    const float* x    = (const float*)d_in[0];
    const float* sre  = (const float*)d_in[1];
    const float* sim_ = (const float*)d_in[2];
    const float* Wdt  = (const float*)d_in[3];
    const float* bdt  = (const float*)d_in[4];
    const float* Wph  = (const float*)d_in[5];
    const float* bph  = (const float*)d_in[6];
    const float* WB   = (const float*)d_in[7];
    const float* WC   = (const float*)d_in[8];
    const float* Ar   = (const float*)d_in[9];
    const float* Ai   = (const float*)d_in[10];

    float* out = (float*)d_out;
    float* nre = out + (size_t)BATCH * DMODEL;
    float* nim = nre + (size_t)BATCH * RANK;

    const int smem1 = SMEM1;                     // 56320 B
    const int smem2 = 2 * 128 * LDK2H * 2;       // 36864 B

    cudaFuncSetAttribute(proj_kernel, cudaFuncAttributeMaxDynamicSharedMemorySize, smem1);
    cudaFuncSetAttribute(out_kernel,  cudaFuncAttributeMaxDynamicSharedMemorySize, smem2);

    convert_weights<<<(NPROJ * DMODEL / 4 + 255) / 256, 256>>>(Wdt, Wph, WB, WC);
    proj_kernel<<<BATCH / 64, 256, smem1>>>(x, sre, sim_, bdt, bph, Ar, Ai, nre, nim);
    out_kernel<<<dim3(BATCH / 128, DMODEL / 128), 256, smem2>>>(out);
}

// round 14
// speedup vs baseline: 2.0202x; 1.1208x over previous
#include <cuda_runtime.h>
#include <cuda_fp16.h>
#include <cstdint>
#include <math.h>

#define BATCH  16384
#define DMODEL 2048
#define RANK   64
#define NPROJ  192

// fp16 weight mirrors (static scratch; no allocation)
__device__ __half d_Wh[NPROJ * DMODEL];      // concat [Wdt;Wph;WB], 768 KB
__device__ __half d_WCh[DMODEL * RANK];      // 256 KB

// ---------------------------------------------------------------------------
// helpers
// ---------------------------------------------------------------------------
__device__ __forceinline__ uint32_t smem_u32(const void* p) {
    uint32_t a;
    asm("{ .reg .u64 t; cvta.to.shared.u64 t, %1; cvt.u32.u64 %0, t; }"
        : "=r"(a) : "l"(p));
    return a;
}
__device__ __forceinline__ void mma_f16(float* d, const uint32_t* A, const uint32_t* B) {
    asm volatile(
        "mma.sync.aligned.m16n8k16.row.col.f32.f16.f16.f32 "
        "{%0,%1,%2,%3}, {%4,%5,%6,%7}, {%8,%9}, {%0,%1,%2,%3};\n"
        : "+f"(d[0]), "+f"(d[1]), "+f"(d[2]), "+f"(d[3])
        : "r"(A[0]), "r"(A[1]), "r"(A[2]), "r"(A[3]), "r"(B[0]), "r"(B[1]));
}
__device__ __forceinline__ void ldsm_x4(uint32_t* r, uint32_t addr) {
    asm volatile("ldmatrix.sync.aligned.m8n8.x4.shared.b16 {%0,%1,%2,%3}, [%4];"
                 : "=r"(r[0]), "=r"(r[1]), "=r"(r[2]), "=r"(r[3]) : "r"(addr));
}
__device__ __forceinline__ void ldsm_x2(uint32_t* r, uint32_t addr) {
    asm volatile("ldmatrix.sync.aligned.m8n8.x2.shared.b16 {%0,%1}, [%2];"
                 : "=r"(r[0]), "=r"(r[1]) : "r"(addr));
}
__device__ __forceinline__ uint2 pack_h4(float4 v) {
    __half2 h0 = __floats2half2_rn(v.x, v.y);
    __half2 h1 = __floats2half2_rn(v.z, v.w);
    uint2 u;
    u.x = *reinterpret_cast<uint32_t*>(&h0);
    u.y = *reinterpret_cast<uint32_t*>(&h1);
    return u;
}
__device__ __forceinline__ void cp16(uint32_t saddr, const void* g) {
    asm volatile("cp.async.cg.shared.global [%0], [%1], 16;" :: "r"(saddr), "l"(g));
}
#define CP_COMMIT() asm volatile("cp.async.commit_group;" ::: "memory")
#define CP_WAIT1()  asm volatile("cp.async.wait_group 1;"  ::: "memory")
#define CP_WAIT0()  asm volatile("cp.async.wait_group 0;"  ::: "memory")

// ---------------------------------------------------------------------------
// Kernel 0: f32 -> f16 weight conversion (one float4 per thread)
// ---------------------------------------------------------------------------
__global__ void __launch_bounds__(256) convert_weights(
    const float* __restrict__ Wdt, const float* __restrict__ Wph,
    const float* __restrict__ WB,  const float* __restrict__ WC)
{
    int t = blockIdx.x * 256 + threadIdx.x;
    if (t < NPROJ * DMODEL / 4) {              // 98304 float4 -> Wh
        int row = t >> 9;                      // 512 float4 per row
        int c4  = (t & 511) << 2;
        const float* src = (row < 64)  ? (Wdt + (size_t)row * DMODEL)
                         : (row < 128) ? (Wph + (size_t)(row - 64) * DMODEL)
                                       : (WB  + (size_t)(row - 128) * DMODEL);
        float4 v = *reinterpret_cast<const float4*>(src + c4);
        *reinterpret_cast<uint2*>(d_Wh + (size_t)row * DMODEL + c4) = pack_h4(v);
    } else {
        int t2 = t - NPROJ * DMODEL / 4;       // 32768 float4 -> WCh
        if (t2 < DMODEL * RANK / 4) {
            float4 v = *reinterpret_cast<const float4*>(WC + (size_t)t2 * 4);
            *reinterpret_cast<uint2*>(d_WCh + (size_t)t2 * 4) = pack_h4(v);
        }
    }
}

// ---------------------------------------------------------------------------
// Fused kernel: proj GEMM + state update + output GEMM
//   phase A: P = x @ Wcat^T       (64x192 tile, K=2048, cp.async pipeline)
//   phase B: elementwise update -> nre/nim (f32 gmem) + A' (fp16 smem)
//   phase C: out[m0:m0+64, :] = A' @ WC^T   (16 n-tiles of 128, cp.async)
// ---------------------------------------------------------------------------
#define LDKH  40                       // halves per smem row (80 B)
#define A0OFF 0
#define A1OFF 5120
#define B0OFF 10240
#define BBUFB 15360                    // bytes per proj B buffer
#define LDP   194
#define NKT   (DMODEL / 32)
// phase C layout
#define LDOH   72                      // halves per row (144 B, conflict-free)
#define OB_BUF 18432                   // bytes per WC tile buffer (128*72*2)
#define APOFF  55296                   // A' fp16 (64 x 72) at 55296..64512
#define SMEM1  64512

__global__ void __launch_bounds__(256, 2) fused_kernel(
    const float* __restrict__ x,
    const float* __restrict__ sre, const float* __restrict__ sim_,
    const float* __restrict__ bdt, const float* __restrict__ bph,
    const float* __restrict__ Areal, const float* __restrict__ Aimag,
    float* __restrict__ out,
    float* __restrict__ nre, float* __restrict__ nim)
{
    extern __shared__ float smemf[];
    __half* smh = reinterpret_cast<__half*>(smemf);
    const uint32_t sbase = smem_u32(smemf);

    const int tid  = threadIdx.x;
    const int wid  = tid >> 5;
    const int lane = tid & 31;
    const int wm   = wid >> 2;     // 0..1
    const int wn   = wid & 3;      // 0..3
    const int m0   = blockIdx.x * 64;

    // ================= phase A: projection GEMM =================
    const int part = lane >> 3, rA = lane & 7;
    uint32_t aLm[2];
    #pragma unroll
    for (int mt = 0; mt < 2; mt++) {
        int row  = wm * 32 + mt * 16 + (part & 1) * 8 + rA;
        int colh = (part >> 1) * 8;
        aLm[mt] = sbase + A0OFF + (uint32_t)(row * LDKH + colh) * 2;
    }
    const int l16 = lane & 15;
    uint32_t bLm[6];
    #pragma unroll
    for (int nt = 0; nt < 6; nt++) {
        int row  = wn * 48 + nt * 8 + (l16 & 7);
        int colh = (l16 >> 3) * 8;
        bLm[nt] = sbase + B0OFF + (uint32_t)(row * LDKH + colh) * 2;
    }

    const float* aP[2]; int aOfs[2];
    #pragma unroll
    for (int i = 0; i < 2; i++) {
        int idx = tid + i * 256;
        int row = idx >> 3, c4 = (idx & 7) << 2;
        aP[i]   = x + (size_t)(m0 + row) * DMODEL + c4;
        aOfs[i] = row * LDKH + c4;
    }
    const __half* bG[3]; uint32_t bSts[3];
    #pragma unroll
    for (int i = 0; i < 3; i++) {
        int c   = tid + i * 256;
        int row = c >> 2, ch = c & 3;
        bG[i]   = d_Wh + (size_t)row * DMODEL + ch * 8;
        bSts[i] = sbase + B0OFF + (uint32_t)(row * LDKH + ch * 8) * 2;
    }

    float acc[2][6][4];
    #pragma unroll
    for (int i = 0; i < 2; i++)
        #pragma unroll
        for (int j = 0; j < 6; j++)
            #pragma unroll
            for (int k = 0; k < 4; k++) acc[i][j][k] = 0.f;

    float4 ra[2];
    auto ldgA = [&](int kt) {
        #pragma unroll
        for (int i = 0; i < 2; i++)
            ra[i] = *reinterpret_cast<const float4*>(aP[i] + kt * 32);
    };
    auto stsA = [&](int ab) {
        __half* dst = smh + (ab ? A1OFF / 2 : 0);
        #pragma unroll
        for (int i = 0; i < 2; i++)
            *reinterpret_cast<uint2*>(dst + aOfs[i]) = pack_h4(ra[i]);
    };
    auto cpB = [&](int kt, int b3) {
        const uint32_t so = (uint32_t)b3 * BBUFB;
        #pragma unroll
        for (int i = 0; i < 3; i++)
            cp16(bSts[i] + so, bG[i] + kt * 32);
        CP_COMMIT();
    };

    cpB(0, 0);
    cpB(1, 1);
    ldgA(0); stsA(0);
    ldgA(1);
    CP_WAIT1();
    __syncthreads();

    int cur3 = 0;
    for (int kt = 0; kt < NKT; ++kt) {
        const int ab = kt & 1;
        const uint32_t aOffB = ab ? (uint32_t)A1OFF : 0u;
        const uint32_t bOffB = (uint32_t)cur3 * BBUFB;
        #pragma unroll
        for (int k16 = 0; k16 < 2; k16++) {
            const uint32_t kB = (uint32_t)k16 * 32;
            uint32_t afr[2][4], bfr[6][2];
            #pragma unroll
            for (int mt = 0; mt < 2; mt++) ldsm_x4(afr[mt], aLm[mt] + aOffB + kB);
            #pragma unroll
            for (int nt = 0; nt < 6; nt++) ldsm_x2(bfr[nt], bLm[nt] + bOffB + kB);
            #pragma unroll
            for (int mt = 0; mt < 2; mt++)
                #pragma unroll
                for (int nt = 0; nt < 6; nt++)
                    mma_f16(acc[mt][nt], afr[mt], bfr[nt]);
        }
        if (kt + 1 < NKT) {
            stsA(ab ^ 1);
            if (kt + 2 < NKT) {
                int nxt = cur3 + 2; if (nxt >= 3) nxt -= 3;
                cpB(kt + 2, nxt);
                ldgA(kt + 2);
                CP_WAIT1();
            } else {
                CP_WAIT0();
            }
            __syncthreads();
        }
        cur3 = (cur3 + 1 == 3) ? 0 : cur3 + 1;
    }
    __syncthreads();

    // ================= stage P (64 x 192, f32) =================
    const int g = lane >> 2, t = lane & 3;
    float* P = smemf;
    #pragma unroll
    for (int mt = 0; mt < 2; mt++) {
        int r0 = wm * 32 + mt * 16 + g;
        #pragma unroll
        for (int nt = 0; nt < 6; nt++) {
            int c0 = wn * 48 + nt * 8 + 2 * t;
            *reinterpret_cast<float2*>(P + r0 * LDP + c0) =
                make_float2(acc[mt][nt][0], acc[mt][nt][1]);
            *reinterpret_cast<float2*>(P + (r0 + 8) * LDP + c0) =
                make_float2(acc[mt][nt][2], acc[mt][nt][3]);
        }
    }
    __syncthreads();

    // ================= phase B: elementwise state update =================
    {
        const float PI_F = 3.14159265358979323846f;
        const int r = tid & 63;
        const float bdt_r = bdt[r];
        const float bph_r = bph[r];
        const float eA_r  = __expf(Areal[r]);
        const float Ai_r  = Aimag[r];
        __half* Ap = smh + APOFF / 2;          // A' fp16 64 x LDOH

        #pragma unroll
        for (int i = 0; i < 16; i++) {
            int idx  = tid + i * 256;
            int row  = idx >> 6;
            int grow = m0 + row;

            float zdt   = P[row * LDP + r] + bdt_r;
            float dt    = (zdt > 15.f) ? zdt : __logf(1.f + __expf(zdt));
            float zph   = P[row * LDP + 64 + r] + bph_r;
            // tanh via exp (accurate to ~1e-6)
            float e2z   = __expf(2.f * zph);
            float th    = 1.f - __fdividef(2.f, 1.f + e2z);
            float phase = th * PI_F;
            float decay = __expf(-dt * eA_r);
            float angle = fmaf(dt, Ai_r, phase);
            float Bv    = P[row * LDP + 128 + r];

            float sn = __sinf(angle);
            float cs = __cosf(angle);

            float a_ = sre[(size_t)grow * RANK + r];
            float b_ = sim_[(size_t)grow * RANK + r];

            float vre = fmaf(a_ * cs - b_ * sn, decay, Bv);
            nre[(size_t)grow * RANK + r] = vre;
            nim[(size_t)grow * RANK + r] = (a_ * sn + b_ * cs) * decay;
            Ap[row * LDOH + r] = __float2half(vre);
        }
    }
    __syncthreads();

    // ================= phase C: out = A' @ WC^T =================
    // A' : 64 x 64 fp16 at APOFF.  WC tiles: 128 rows x 64 halves, triple buf.
    uint32_t aLm2[2];
    #pragma unroll
    for (int mt = 0; mt < 2; mt++) {
        int row  = wm * 32 + mt * 16 + (part & 1) * 8 + rA;
        int colh = (part >> 1) * 8;
        aLm2[mt] = sbase + APOFF + (uint32_t)(row * LDOH + colh) * 2;
    }
    uint32_t bLm2[4];
    #pragma unroll
    for (int nt = 0; nt < 4; nt++) {
        int row  = wn * 32 + nt * 8 + (l16 & 7);
        int colh = (l16 >> 3) * 8;
        bLm2[nt] = sbase + (uint32_t)(row * LDOH + colh) * 2;
    }

    auto cpWC = [&](int t128, int b3) {
        const uint32_t so = (uint32_t)b3 * OB_BUF;
        #pragma unroll
        for (int i = 0; i < 4; i++) {
            int c = tid + i * 256;             // 1024 x 16B chunks
            int row = c >> 3, ch = c & 7;
            cp16(sbase + so + (uint32_t)(row * LDOH + ch * 8) * 2,
                 d_WCh + ((size_t)t128 * 128 + row) * RANK + ch * 8);
        }
        CP_COMMIT();
    };

    cpWC(0, 0);
    cpWC(1, 1);
    CP_WAIT1();
    __syncthreads();

    int c3 = 0;
    for (int t128 = 0; t128 < 16; ++t128) {
        float acc2[2][4][4];
        #pragma unroll
        for (int i = 0; i < 2; i++)
            #pragma unroll
            for (int j = 0; j < 4; j++)
                #pragma unroll
                for (int k = 0; k < 4; k++) acc2[i][j][k] = 0.f;

        const uint32_t so = (uint32_t)c3 * OB_BUF;
        #pragma unroll
        for (int k16 = 0; k16 < 4; k16++) {
            const uint32_t kB = (uint32_t)k16 * 32;
            uint32_t afr[2][4], bfr[4][2];
            #pragma unroll
            for (int mt = 0; mt < 2; mt++) ldsm_x4(afr[mt], aLm2[mt] + kB);
            #pragma unroll
            for (int nt = 0; nt < 4; nt++) ldsm_x2(bfr[nt], bLm2[nt] + so + kB);
            #pragma unroll
            for (int mt = 0; mt < 2; mt++)
                #pragma unroll
                for (int nt = 0; nt < 4; nt++)
                    mma_f16(acc2[mt][nt], afr[mt], bfr[nt]);
        }

        const int n0 = t128 * 128;
        #pragma unroll
        for (int mt = 0; mt < 2; mt++) {
            int row = m0 + wm * 32 + mt * 16 + g;
            #pragma unroll
            for (int nt = 0; nt < 4; nt++) {
                int col = n0 + wn * 32 + nt * 8 + 2 * t;
                *reinterpret_cast<float2*>(out + (size_t)row * DMODEL + col) =
                    make_float2(acc2[mt][nt][0], acc2[mt][nt][1]);
                *reinterpret_cast<float2*>(out + (size_t)(row + 8) * DMODEL + col) =
                    make_float2(acc2[mt][nt][2], acc2[mt][nt][3]);
            }
        }

        if (t128 + 2 < 16) {
            int nxt = c3 + 2; if (nxt >= 3) nxt -= 3;
            cpWC(t128 + 2, nxt);
            CP_WAIT1();
            __syncthreads();
        } else if (t128 + 1 < 16) {
            CP_WAIT0();
            __syncthreads();
        }
        c3 = (c3 + 1 == 3) ? 0 : c3 + 1;
    }
}

// ---------------------------------------------------------------------------
// launch
// ---------------------------------------------------------------------------
extern "C" void kernel_launch(void* const* d_in, const int* in_sizes, int n_in,
                              void* d_out, int out_size)
{
    const float* x    = (const float*)d_in[0];
    const float* sre  = (const float*)d_in[1];
    const float* sim_ = (const float*)d_in[2];
    const float* Wdt  = (const float*)d_in[3];
    const float* bdt  = (const float*)d_in[4];
    const float* Wph  = (const float*)d_in[5];
    const float* bph  = (const float*)d_in[6];
    const float* WB   = (const float*)d_in[7];
    const float* WC   = (const float*)d_in[8];
    const float* Ar   = (const float*)d_in[9];
    const float* Ai   = (const float*)d_in[10];

    float* out = (float*)d_out;
    float* nre = out + (size_t)BATCH * DMODEL;
    float* nim = nre + (size_t)BATCH * RANK;

    cudaFuncSetAttribute(fused_kernel, cudaFuncAttributeMaxDynamicSharedMemorySize, SMEM1);

    convert_weights<<<512, 256>>>(Wdt, Wph, WB, WC);
    fused_kernel<<<BATCH / 64, 256, SMEM1>>>(x, sre, sim_, bdt, bph, Ar, Ai,
                                             out, nre, nim);
}

// round 15
// speedup vs baseline: 2.1997x; 1.0888x over previous
#include <cuda_runtime.h>
#include <cuda_fp16.h>
#include <cstdint>
#include <math.h>

#define BATCH  16384
#define DMODEL 2048
#define RANK   64
#define NPROJ  192

// fp16 weight mirrors (static scratch; no allocation)
__device__ __half d_Wh[NPROJ * DMODEL];      // concat [Wdt;Wph;WB], 768 KB
__device__ __half d_WCh[DMODEL * RANK];      // 256 KB

// ---------------------------------------------------------------------------
// helpers
// ---------------------------------------------------------------------------
__device__ __forceinline__ uint32_t smem_u32(const void* p) {
    uint32_t a;
    asm("{ .reg .u64 t; cvta.to.shared.u64 t, %1; cvt.u32.u64 %0, t; }"
        : "=r"(a) : "l"(p));
    return a;
}
__device__ __forceinline__ void mma_f16(float* d, const uint32_t* A, const uint32_t* B) {
    asm volatile(
        "mma.sync.aligned.m16n8k16.row.col.f32.f16.f16.f32 "
        "{%0,%1,%2,%3}, {%4,%5,%6,%7}, {%8,%9}, {%0,%1,%2,%3};\n"
        : "+f"(d[0]), "+f"(d[1]), "+f"(d[2]), "+f"(d[3])
        : "r"(A[0]), "r"(A[1]), "r"(A[2]), "r"(A[3]), "r"(B[0]), "r"(B[1]));
}
__device__ __forceinline__ void ldsm_x4(uint32_t* r, uint32_t addr) {
    asm volatile("ldmatrix.sync.aligned.m8n8.x4.shared.b16 {%0,%1,%2,%3}, [%4];"
                 : "=r"(r[0]), "=r"(r[1]), "=r"(r[2]), "=r"(r[3]) : "r"(addr));
}
__device__ __forceinline__ void ldsm_x2(uint32_t* r, uint32_t addr) {
    asm volatile("ldmatrix.sync.aligned.m8n8.x2.shared.b16 {%0,%1}, [%2];"
                 : "=r"(r[0]), "=r"(r[1]) : "r"(addr));
}
__device__ __forceinline__ uint2 pack_h4(float4 v) {
    __half2 h0 = __floats2half2_rn(v.x, v.y);
    __half2 h1 = __floats2half2_rn(v.z, v.w);
    uint2 u;
    u.x = *reinterpret_cast<uint32_t*>(&h0);
    u.y = *reinterpret_cast<uint32_t*>(&h1);
    return u;
}
__device__ __forceinline__ void cp16(uint32_t saddr, const void* g) {
    asm volatile("cp.async.cg.shared.global [%0], [%1], 16;" :: "r"(saddr), "l"(g));
}
#define CP_COMMIT() asm volatile("cp.async.commit_group;" ::: "memory")
#define CP_WAIT1()  asm volatile("cp.async.wait_group 1;"  ::: "memory")
#define CP_WAIT0()  asm volatile("cp.async.wait_group 0;"  ::: "memory")

// ---------------------------------------------------------------------------
// Kernel 0: f32 -> f16 weight conversion (one float4 per thread)
// ---------------------------------------------------------------------------
__global__ void __launch_bounds__(256) convert_weights(
    const float* __restrict__ Wdt, const float* __restrict__ Wph,
    const float* __restrict__ WB,  const float* __restrict__ WC)
{
    int t = blockIdx.x * 256 + threadIdx.x;
    if (t < NPROJ * DMODEL / 4) {              // 98304 float4 -> Wh
        int row = t >> 9;
        int c4  = (t & 511) << 2;
        const float* src = (row < 64)  ? (Wdt + (size_t)row * DMODEL)
                         : (row < 128) ? (Wph + (size_t)(row - 64) * DMODEL)
                                       : (WB  + (size_t)(row - 128) * DMODEL);
        float4 v = *reinterpret_cast<const float4*>(src + c4);
        *reinterpret_cast<uint2*>(d_Wh + (size_t)row * DMODEL + c4) = pack_h4(v);
    } else {
        int t2 = t - NPROJ * DMODEL / 4;       // 32768 float4 -> WCh
        if (t2 < DMODEL * RANK / 4) {
            float4 v = *reinterpret_cast<const float4*>(WC + (size_t)t2 * 4);
            *reinterpret_cast<uint2*>(d_WCh + (size_t)t2 * 4) = pack_h4(v);
        }
    }
}

// ---------------------------------------------------------------------------
// Fused kernel: proj GEMM (BK=64) + state update + output GEMM
// ---------------------------------------------------------------------------
#define LDKH  72                       // halves per smem row (144 B, conflict-free)
#define A0OFF 0
#define A1OFF 9216                     // 64*72*2
#define B0OFF 18432
#define BBUFB 27648                    // 192*72*2
#define LDP   194
#define NKT   (DMODEL / 64)            // 32 K-tiles
// phase C
#define LDOH   72
#define OB_BUF 18432                   // 128*72*2, buffers live at B0OFF
#define APOFF  101376                  // after B buffers (18432 + 3*27648)
#define SMEM1  110592                  // APOFF + 64*72*2

__global__ void __launch_bounds__(256, 2) fused_kernel(
    const float* __restrict__ x,
    const float* __restrict__ sre, const float* __restrict__ sim_,
    const float* __restrict__ bdt, const float* __restrict__ bph,
    const float* __restrict__ Areal, const float* __restrict__ Aimag,
    float* __restrict__ out,
    float* __restrict__ nre, float* __restrict__ nim)
{
    extern __shared__ float smemf[];
    __half* smh = reinterpret_cast<__half*>(smemf);
    const uint32_t sbase = smem_u32(smemf);

    const int tid  = threadIdx.x;
    const int wid  = tid >> 5;
    const int lane = tid & 31;
    const int wm   = wid >> 2;     // 0..1
    const int wn   = wid & 3;      // 0..3
    const int m0   = blockIdx.x * 64;

    // ================= phase A: projection GEMM (BK=64) =================
    const int part = lane >> 3, rA = lane & 7;
    uint32_t aLm[2];
    #pragma unroll
    for (int mt = 0; mt < 2; mt++) {
        int row  = wm * 32 + mt * 16 + (part & 1) * 8 + rA;
        int colh = (part >> 1) * 8;
        aLm[mt] = sbase + A0OFF + (uint32_t)(row * LDKH + colh) * 2;
    }
    const int l16 = lane & 15;
    uint32_t bLm[6];
    #pragma unroll
    for (int nt = 0; nt < 6; nt++) {
        int row  = wn * 48 + nt * 8 + (l16 & 7);
        int colh = (l16 >> 3) * 8;
        bLm[nt] = sbase + B0OFF + (uint32_t)(row * LDKH + colh) * 2;
    }

    // A (x, f32): 64 rows x 16 float4 = 1024 -> 4/thread
    const float* aP[4]; int aOfs[4];
    #pragma unroll
    for (int i = 0; i < 4; i++) {
        int idx = tid + i * 256;
        int row = idx >> 4, c4 = (idx & 15) << 2;
        aP[i]   = x + (size_t)(m0 + row) * DMODEL + c4;
        aOfs[i] = row * LDKH + c4;
    }
    // B (Wh, fp16): 192 rows x 8 chunks(16B) = 1536 -> 6/thread
    const __half* bG[6]; uint32_t bSts[6];
    #pragma unroll
    for (int i = 0; i < 6; i++) {
        int c   = tid + i * 256;
        int row = c >> 3, ch = c & 7;
        bG[i]   = d_Wh + (size_t)row * DMODEL + ch * 8;
        bSts[i] = sbase + B0OFF + (uint32_t)(row * LDKH + ch * 8) * 2;
    }

    float acc[2][6][4];
    #pragma unroll
    for (int i = 0; i < 2; i++)
        #pragma unroll
        for (int j = 0; j < 6; j++)
            #pragma unroll
            for (int k = 0; k < 4; k++) acc[i][j][k] = 0.f;

    float4 ra[4];
    auto ldgA = [&](int kt) {
        #pragma unroll
        for (int i = 0; i < 4; i++)
            ra[i] = *reinterpret_cast<const float4*>(aP[i] + kt * 64);
    };
    auto stsA = [&](int ab) {
        __half* dst = smh + (ab ? A1OFF / 2 : 0);
        #pragma unroll
        for (int i = 0; i < 4; i++)
            *reinterpret_cast<uint2*>(dst + aOfs[i]) = pack_h4(ra[i]);
    };
    auto cpB = [&](int kt, int b3) {
        const uint32_t so = (uint32_t)b3 * BBUFB;
        #pragma unroll
        for (int i = 0; i < 6; i++)
            cp16(bSts[i] + so, bG[i] + kt * 64);
        CP_COMMIT();
    };

    cpB(0, 0);
    cpB(1, 1);
    ldgA(0); stsA(0);
    ldgA(1);
    CP_WAIT1();
    __syncthreads();

    int cur3 = 0;
    for (int kt = 0; kt < NKT; ++kt) {
        const int ab = kt & 1;
        const uint32_t aOffB = ab ? (uint32_t)A1OFF : 0u;
        const uint32_t bOffB = (uint32_t)cur3 * BBUFB;
        #pragma unroll
        for (int k16 = 0; k16 < 4; k16++) {
            const uint32_t kB = (uint32_t)k16 * 32;
            uint32_t afr[2][4], bfr[6][2];
            #pragma unroll
            for (int mt = 0; mt < 2; mt++) ldsm_x4(afr[mt], aLm[mt] + aOffB + kB);
            #pragma unroll
            for (int nt = 0; nt < 6; nt++) ldsm_x2(bfr[nt], bLm[nt] + bOffB + kB);
            #pragma unroll
            for (int mt = 0; mt < 2; mt++)
                #pragma unroll
                for (int nt = 0; nt < 6; nt++)
                    mma_f16(acc[mt][nt], afr[mt], bfr[nt]);
        }
        if (kt + 1 < NKT) {
            stsA(ab ^ 1);
            if (kt + 2 < NKT) {
                int nxt = cur3 + 2; if (nxt >= 3) nxt -= 3;
                cpB(kt + 2, nxt);
                ldgA(kt + 2);
                CP_WAIT1();
            } else {
                CP_WAIT0();
            }
            __syncthreads();
        }
        cur3 = (cur3 + 1 == 3) ? 0 : cur3 + 1;
    }
    __syncthreads();

    // ================= stage P (64 x 192, f32) =================
    const int g = lane >> 2, t = lane & 3;
    float* P = smemf;
    #pragma unroll
    for (int mt = 0; mt < 2; mt++) {
        int r0 = wm * 32 + mt * 16 + g;
        #pragma unroll
        for (int nt = 0; nt < 6; nt++) {
            int c0 = wn * 48 + nt * 8 + 2 * t;
            *reinterpret_cast<float2*>(P + r0 * LDP + c0) =
                make_float2(acc[mt][nt][0], acc[mt][nt][1]);
            *reinterpret_cast<float2*>(P + (r0 + 8) * LDP + c0) =
                make_float2(acc[mt][nt][2], acc[mt][nt][3]);
        }
    }
    __syncthreads();

    // ================= phase B: elementwise state update =================
    {
        const float PI_F = 3.14159265358979323846f;
        const int r = tid & 63;
        const float bdt_r = bdt[r];
        const float bph_r = bph[r];
        const float eA_r  = __expf(Areal[r]);
        const float Ai_r  = Aimag[r];
        __half* Ap = smh + APOFF / 2;

        #pragma unroll
        for (int i = 0; i < 16; i++) {
            int idx  = tid + i * 256;
            int row  = idx >> 6;
            int grow = m0 + row;

            float zdt   = P[row * LDP + r] + bdt_r;
            float dt    = (zdt > 15.f) ? zdt : __logf(1.f + __expf(zdt));
            float zph   = P[row * LDP + 64 + r] + bph_r;
            float e2z   = __expf(2.f * zph);
            float th    = 1.f - __fdividef(2.f, 1.f + e2z);
            float phase = th * PI_F;
            float decay = __expf(-dt * eA_r);
            float angle = fmaf(dt, Ai_r, phase);
            float Bv    = P[row * LDP + 128 + r];

            float sn = __sinf(angle);
            float cs = __cosf(angle);

            float a_ = sre[(size_t)grow * RANK + r];
            float b_ = sim_[(size_t)grow * RANK + r];

            float vre = fmaf(a_ * cs - b_ * sn, decay, Bv);
            nre[(size_t)grow * RANK + r] = vre;
            nim[(size_t)grow * RANK + r] = (a_ * sn + b_ * cs) * decay;
            Ap[row * LDOH + r] = __float2half(vre);
        }
    }
    __syncthreads();

    // ================= phase C: out = A' @ WC^T =================
    uint32_t aLm2[2];
    #pragma unroll
    for (int mt = 0; mt < 2; mt++) {
        int row  = wm * 32 + mt * 16 + (part & 1) * 8 + rA;
        int colh = (part >> 1) * 8;
        aLm2[mt] = sbase + APOFF + (uint32_t)(row * LDOH + colh) * 2;
    }
    uint32_t bLm2[4];
    #pragma unroll
    for (int nt = 0; nt < 4; nt++) {
        int row  = wn * 32 + nt * 8 + (l16 & 7);
        int colh = (l16 >> 3) * 8;
        bLm2[nt] = sbase + B0OFF + (uint32_t)(row * LDOH + colh) * 2;
    }

    auto cpWC = [&](int t128, int b3) {
        const uint32_t so = (uint32_t)B0OFF + (uint32_t)b3 * OB_BUF;
        #pragma unroll
        for (int i = 0; i < 4; i++) {
            int c = tid + i * 256;
            int row = c >> 3, ch = c & 7;
            cp16(sbase + so + (uint32_t)(row * LDOH + ch * 8) * 2,
                 d_WCh + ((size_t)t128 * 128 + row) * RANK + ch * 8);
        }
        CP_COMMIT();
    };

    cpWC(0, 0);
    cpWC(1, 1);
    CP_WAIT1();
    __syncthreads();

    int c3 = 0;
    for (int t128 = 0; t128 < 16; ++t128) {
        float acc2[2][4][4];
        #pragma unroll
        for (int i = 0; i < 2; i++)
            #pragma unroll
            for (int j = 0; j < 4; j++)
                #pragma unroll
                for (int k = 0; k < 4; k++) acc2[i][j][k] = 0.f;

        const uint32_t so = (uint32_t)c3 * OB_BUF;
        #pragma unroll
        for (int k16 = 0; k16 < 4; k16++) {
            const uint32_t kB = (uint32_t)k16 * 32;
            uint32_t afr[2][4], bfr[4][2];
            #pragma unroll
            for (int mt = 0; mt < 2; mt++) ldsm_x4(afr[mt], aLm2[mt] + kB);
            #pragma unroll
            for (int nt = 0; nt < 4; nt++) ldsm_x2(bfr[nt], bLm2[nt] + so + kB);
            #pragma unroll
            for (int mt = 0; mt < 2; mt++)
                #pragma unroll
                for (int nt = 0; nt < 4; nt++)
                    mma_f16(acc2[mt][nt], afr[mt], bfr[nt]);
        }

        const int n0 = t128 * 128;
        #pragma unroll
        for (int mt = 0; mt < 2; mt++) {
            int row = m0 + wm * 32 + mt * 16 + g;
            #pragma unroll
            for (int nt = 0; nt < 4; nt++) {
                int col = n0 + wn * 32 + nt * 8 + 2 * t;
                *reinterpret_cast<float2*>(out + (size_t)row * DMODEL + col) =
                    make_float2(acc2[mt][nt][0], acc2[mt][nt][1]);
                *reinterpret_cast<float2*>(out + (size_t)(row + 8) * DMODEL + col) =
                    make_float2(acc2[mt][nt][2], acc2[mt][nt][3]);
            }
        }

        if (t128 + 2 < 16) {
            int nxt = c3 + 2; if (nxt >= 3) nxt -= 3;
            cpWC(t128 + 2, nxt);
            CP_WAIT1();
            __syncthreads();
        } else if (t128 + 1 < 16) {
            CP_WAIT0();
            __syncthreads();
        }
        c3 = (c3 + 1 == 3) ? 0 : c3 + 1;
    }
}

// ---------------------------------------------------------------------------
// launch
// ---------------------------------------------------------------------------
extern "C" void kernel_launch(void* const* d_in, const int* in_sizes, int n_in,
                              void* d_out, int out_size)
{
    const float* x    = (const float*)d_in[0];
    const float* sre  = (const float*)d_in[1];
    const float* sim_ = (const float*)d_in[2];
    const float* Wdt  = (const float*)d_in[3];
    const float* bdt  = (const float*)d_in[4];
    const float* Wph  = (const float*)d_in[5];
    const float* bph  = (const float*)d_in[6];
    const float* WB   = (const float*)d_in[7];
    const float* WC   = (const float*)d_in[8];
    const float* Ar   = (const float*)d_in[9];
    const float* Ai   = (const float*)d_in[10];

    float* out = (float*)d_out;
    float* nre = out + (size_t)BATCH * DMODEL;
    float* nim = nre + (size_t)BATCH * RANK;

    cudaFuncSetAttribute(fused_kernel, cudaFuncAttributeMaxDynamicSharedMemorySize, SMEM1);

    convert_weights<<<512, 256>>>(Wdt, Wph, WB, WC);
    fused_kernel<<<BATCH / 64, 256, SMEM1>>>(x, sre, sim_, bdt, bph, Ar, Ai,
                                             out, nre, nim);
}